// round 15
// baseline (speedup 1.0000x reference)
#include <cuda_runtime.h>
#include <cuda_bf16.h>
#include <math.h>
#include <float.h>

#define B_    512
#define T_    247
#define C_    64
#define NTF_  200
#define LPOOL 254
#define MROWS (B_*T_)      // 126464
#define MBLK  988          // MROWS/128

typedef unsigned long long u64;

// ---------------- scratch ----------------
__device__ float g_pooled[B_*C_*LPOOL];
__device__ float g_xproj [(size_t)MROWS*512];
__device__ float g_values[MROWS*128];
__device__ float g_hT    [2*B_*64];
__device__ float g_query [B_*128];
__device__ float g_score [MROWS*NTF_];
__device__ float g_ctx   [B_*NTF_*128];
__device__ float g_W2T [128*128];
__device__ float g_biasIH[512];
// fragment-ordered operand arrays (hi / lo bf16x2 words)
__device__ unsigned g_xAfh[(size_t)MBLK*4*8*32*4], g_xAfl[(size_t)MBLK*4*8*32*4];
__device__ unsigned g_EAfh[(size_t)B_*2*8*8*32*4], g_EAfl[(size_t)B_*2*8*8*32*4];
__device__ unsigned g_WIHfh[4*64*32*2],  g_WIHfl[4*64*32*2];
__device__ unsigned g_W1fh [8*16*32*2],  g_W1fl [8*16*32*2];
__device__ unsigned g_Vfh  [8*32*32*2],  g_Vfl  [8*32*32*2];
__device__ unsigned g_c1fh [32*8*32*2],  g_c1fl [32*8*32*2];

__device__ __forceinline__ float sigf(float x){ return 1.f/(1.f+__expf(-x)); }

// ---- packed fp32x2 helpers (FFMA2) — lstm ----
__device__ __forceinline__ u64 ffma2(u64 a, u64 b, u64 c){
    u64 d;
    asm("fma.rn.f32x2 %0, %1, %2, %3;" : "=l"(d) : "l"(a), "l"(b), "l"(c));
    return d;
}
__device__ __forceinline__ u64 pack2(float x, float y){
    u64 d;
    asm("mov.b64 %0, {%1, %2};" : "=l"(d) : "f"(x), "f"(y));
    return d;
}
__device__ __forceinline__ float2 unpack2(u64 d){
    float2 f;
    asm("mov.b64 {%0, %1}, %2;" : "=f"(f.x), "=f"(f.y) : "l"(d));
    return f;
}

// ---- bf16 2-term split ----
__device__ __forceinline__ void split2(float x0, float x1, unsigned &wh, unsigned &wl){
    unsigned hh;
    asm("cvt.rn.bf16x2.f32 %0, %1, %2;" : "=r"(hh) : "f"(x1), "f"(x0));
    float h0 = __uint_as_float(hh << 16);
    float h1 = __uint_as_float(hh & 0xffff0000u);
    float r0 = x0 - h0, r1 = x1 - h1;
    asm("cvt.rn.bf16x2.f32 %0, %1, %2;" : "=r"(wl) : "f"(r1), "f"(r0));
    wh = hh;
}
__device__ __forceinline__ void mma16(float *d, const uint4 &a, const uint2 &b){
    asm volatile("mma.sync.aligned.m16n8k16.row.col.f32.bf16.bf16.f32 "
        "{%0,%1,%2,%3}, {%4,%5,%6,%7}, {%8,%9}, {%0,%1,%2,%3};"
        : "+f"(d[0]), "+f"(d[1]), "+f"(d[2]), "+f"(d[3])
        : "r"(a.x), "r"(a.y), "r"(a.z), "r"(a.w), "r"(b.x), "r"(b.y));
}

// ---- cp.async helpers ----
__device__ __forceinline__ void cpa16(void *smem, const void *gmem){
    unsigned s = (unsigned)__cvta_generic_to_shared(smem);
    asm volatile("cp.async.cg.shared.global [%0], [%1], 16;" :: "r"(s), "l"(gmem));
}
#define CP_COMMIT asm volatile("cp.async.commit_group;" ::: "memory")
#define CP_WAIT0  asm volatile("cp.async.wait_group 0;" ::: "memory")

// smem fragment tiles (A-only and full, single buffer) for conv1/keys/context
struct TSmemA { unsigned Ah[8][32][4], Al[8][32][4]; };
struct TSmem  {
    unsigned Ah[8][32][4], Al[8][32][4];
    unsigned Bh[16][33][2], Bl[16][33][2];
};

__device__ __forceinline__ void astoreW(unsigned (&Ah)[8][32][4], unsigned (&Al)[8][32][4],
                                        int m, int kp, unsigned wh, unsigned wl){
    int mt = m>>4, t = (m&7)*4 + (kp&3);
    int v = ((kp>=4)?2:0) | (((m&15)>=8)?1:0);
    Ah[mt][t][v] = wh; Al[mt][t][v] = wl;
}
__device__ __forceinline__ void bstoreW(unsigned *Bh, unsigned *Bl,
                                        int kp, int n, unsigned wh, unsigned wl){
    int idx = (n>>3)*66 + ((n&7)*4 + (kp&3))*2 + ((kp>=4)?1:0);
    Bh[idx] = wh; Bl[idx] = wl;
}
__device__ __forceinline__ void astoreB(unsigned (&Ah)[8][32][4], unsigned (&Al)[8][32][4],
                                        int m, int kp, float x0, float x1){
    unsigned wh, wl; split2(x0, x1, wh, wl);
    astoreW(Ah, Al, m, kp, wh, wl);
}
__device__ __forceinline__ void bstoreB(unsigned *Bh, unsigned *Bl,
                                        int kp, int n, float x0, float x1){
    unsigned wh, wl; split2(x0, x1, wh, wl);
    bstoreW(Bh, Bl, kp, n, wh, wl);
}

__device__ __forceinline__ void tcomp(const TSmem &S, float (&acc)[4][4][4],
                                      int lane, int wm, int wn)
{
    uint2 bh[4], bl[4];
    #pragma unroll
    for (int j = 0; j < 4; j++){
        int nt = wn*4 + j;
        bh[j] = *(const uint2*)&S.Bh[nt][lane][0];
        bl[j] = *(const uint2*)&S.Bl[nt][lane][0];
    }
    #pragma unroll
    for (int i = 0; i < 4; i++){
        int mt = wm*4 + i;
        uint4 ah = *(const uint4*)&S.Ah[mt][lane][0];
        uint4 al = *(const uint4*)&S.Al[mt][lane][0];
        #pragma unroll
        for (int j = 0; j < 4; j++){
            mma16(acc[i][j], ah, bh[j]);
            mma16(acc[i][j], ah, bl[j]);
            mma16(acc[i][j], al, bh[j]);
        }
    }
}

// ---------------- prep: fragment-ordered weights + W2T + bias ----------------
__global__ void k_prep(const float* __restrict__ W1, const float* __restrict__ W2,
                       const float* __restrict__ V,
                       const float* __restrict__ wih_f, const float* __restrict__ wih_b,
                       const float* __restrict__ bih_f, const float* __restrict__ bhh_f,
                       const float* __restrict__ bih_b, const float* __restrict__ bhh_b,
                       const float* __restrict__ c1w)
{
    int idx = blockIdx.x*blockDim.x + threadIdx.x;
    if (idx < 16384){ int n = idx/128, k = idx%128; g_W2T[k*128+n] = W2[idx]; }
    if (idx < 16384){
        int kp = idx >> 9, n = idx & 511;
        float x0 = (n<256)? wih_f[n*64 + 2*kp]   : wih_b[(n-256)*64 + 2*kp];
        float x1 = (n<256)? wih_f[n*64 + 2*kp+1] : wih_b[(n-256)*64 + 2*kp+1];
        unsigned wh, wl; split2(x0, x1, wh, wl);
        int kc = kp>>3, kpA = kp&7;
        int lane = (n&7)*4 + (kpA&3), v = (kpA>=4)?1:0;
        int d = (((kc*64 + (n>>3))*32 + lane)*2) + v;
        g_WIHfh[d] = wh; g_WIHfl[d] = wl;
    }
    if (idx < 8192){
        int kp = idx >> 7, n = idx & 127;
        unsigned wh, wl; split2(W1[n*128+2*kp], W1[n*128+2*kp+1], wh, wl);
        int kc = kp>>3, kpA = kp&7;
        int lane = (n&7)*4 + (kpA&3), v = (kpA>=4)?1:0;
        int d = (((kc*16 + (n>>3))*32 + lane)*2) + v;
        g_W1fh[d] = wh; g_W1fl[d] = wl;
    }
    if (idx < 64*NTF_){
        int kp = idx / NTF_, n = idx % NTF_;
        unsigned wh, wl; split2(V[n*128+2*kp], V[n*128+2*kp+1], wh, wl);
        int kc = kp>>3, kpA = kp&7;
        int lane = (n&7)*4 + (kpA&3), v = (kpA>=4)?1:0;
        int d = (((kc*32 + (n>>3))*32 + lane)*2) + v;
        g_Vfh[d] = wh; g_Vfl[d] = wl;
    }
    if (idx < 16384){
        int kp = idx >> 6, n = idx & 63;
        unsigned wh, wl; split2(c1w[n*512+2*kp], c1w[n*512+2*kp+1], wh, wl);
        int kc = kp>>3, kpA = kp&7;
        int lane = (n&7)*4 + (kpA&3), v = (kpA>=4)?1:0;
        int d = (((kc*8 + (n>>3))*32 + lane)*2) + v;
        g_c1fh[d] = wh; g_c1fl[d] = wl;
    }
    if (idx < 512){ g_biasIH[idx] = (idx < 256) ? (bih_f[idx] + bhh_f[idx])
                                                : (bih_b[idx-256] + bhh_b[idx-256]); }
}

// ---------------- conv0 ----------------
__global__ void __launch_bounds__(256) k_conv0(
    const float* __restrict__ x, const float* __restrict__ w, const float* __restrict__ cb,
    const float* __restrict__ g, const float* __restrict__ bb,
    const float* __restrict__ mm, const float* __restrict__ vv)
{
    __shared__ float4 xs4[1024];
    int b = blockIdx.x, tid = threadIdx.x;
    const float4* in4 = (const float4*)(x + (size_t)b*4096);
    for (int i = tid; i < 1024; i += 256) xs4[i] = in4[i];

    int c = tid & 63;
    float4 wr[8];
    #pragma unroll
    for (int kk = 0; kk < 8; kk++)
        wr[kk] = make_float4(w[c*32 + 0*8 + kk], w[c*32 + 1*8 + kk],
                             w[c*32 + 2*8 + kk], w[c*32 + 3*8 + kk]);
    float scale = g[c] * rsqrtf(vv[c] + 1e-5f);
    float shift = bb[c] - mm[c]*scale;
    float cbc   = cb[c];
    __syncthreads();

    for (int idx = tid; idx < 64*LPOOL; idx += 256){
        int q = idx >> 6;
        float best = -FLT_MAX;
        #pragma unroll
        for (int dp = 0; dp < 4; dp++){
            int p = 4*q + dp;
            float acc = cbc;
            #pragma unroll
            for (int kk = 0; kk < 8; kk++){
                float4 xv = xs4[p+kk];
                acc += wr[kk].x*xv.x + wr[kk].y*xv.y + wr[kk].z*xv.z + wr[kk].w*xv.w;
            }
            best = fmaxf(best, acc*scale + shift);
        }
        g_pooled[(b*64 + c)*LPOOL + q] = fmaxf(best, 0.f);
    }
}

// ---------------- conv1 GEMM: A smem, B direct frag LDG ----------------
__global__ void __launch_bounds__(256,2) k_conv1(
    const float* __restrict__ cb,
    const float* __restrict__ gg, const float* __restrict__ bb,
    const float* __restrict__ mm, const float* __restrict__ vv)
{
    __shared__ TSmemA S;
    int tid = threadIdx.x, lane = tid&31, w = tid>>5;
    int m0  = blockIdx.x*128;
    float acc[8][4];
    #pragma unroll
    for (int j=0;j<8;j++) for (int v=0;v<4;v++) acc[j][v]=0.f;

    int mA = tid>>3, kpA = tid&7;
    int bz[4], tl[4];
    #pragma unroll
    for (int r = 0; r < 4; r++){
        int gm = m0 + mA + 32*r;
        bz[r] = gm / T_;
        tl[r] = gm - bz[r]*T_;
    }

    float ax0[4], ax1[4];
    {
        int k = 2*kpA;
        #pragma unroll
        for (int r = 0; r < 4; r++){
            int base = (bz[r]*64 + (k>>3))*LPOOL + tl[r] + (k&7);
            ax0[r] = g_pooled[base]; ax1[r] = g_pooled[base+1];
        }
        #pragma unroll
        for (int r = 0; r < 4; r++) astoreB(S.Ah, S.Al, mA+32*r, kpA, ax0[r], ax1[r]);
    }
    __syncthreads();

    for (int c = 0; c < 32; c++){
        if (c < 31){
            int k = (c+1)*16 + 2*kpA;
            #pragma unroll
            for (int r = 0; r < 4; r++){
                int base = (bz[r]*64 + (k>>3))*LPOOL + tl[r] + (k&7);
                ax0[r] = g_pooled[base]; ax1[r] = g_pooled[base+1];
            }
        }
        {
            uint4 ah = *(const uint4*)&S.Ah[w][lane][0];
            uint4 al = *(const uint4*)&S.Al[w][lane][0];
            #pragma unroll
            for (int j = 0; j < 8; j++){
                size_t o = (((size_t)c*8 + j)*32 + lane)*2;
                uint2 bh = *(const uint2*)&g_c1fh[o];
                uint2 bl = *(const uint2*)&g_c1fl[o];
                mma16(acc[j], ah, bh);
                mma16(acc[j], ah, bl);
                mma16(acc[j], al, bh);
            }
        }
        __syncthreads();
        if (c < 31){
            #pragma unroll
            for (int r = 0; r < 4; r++) astoreB(S.Ah, S.Al, mA+32*r, kpA, ax0[r], ax1[r]);
            __syncthreads();
        }
    }
    int g = lane>>2, tc = lane&3;
    #pragma unroll
    for (int j = 0; j < 8; j++){
        #pragma unroll
        for (int r2 = 0; r2 < 2; r2++){
            int row = m0 + w*16 + g + 8*r2;
            int col = j*8 + tc*2;
            float s0 = gg[col]   * rsqrtf(vv[col]   + 1e-5f);
            float s1 = gg[col+1] * rsqrtf(vv[col+1] + 1e-5f);
            float v0 = fmaxf(acc[j][r2*2+0]*s0 + bb[col]   + (cb[col]  -mm[col])  *s0, 0.f);
            float v1 = fmaxf(acc[j][r2*2+1]*s1 + bb[col+1] + (cb[col+1]-mm[col+1])*s1, 0.f);
            unsigned wh, wl; split2(v0, v1, wh, wl);
            int kp = col >> 1, kc = kp>>3, kpA2 = kp&7;
            int mblk = row>>7, mloc = row&127;
            int ln = (mloc&7)*4 + (kpA2&3);
            int v = ((kpA2>=4)?2:0) | (((mloc&15)>=8)?1:0);
            size_t d = ((((size_t)mblk*4 + kc)*8 + (mloc>>4))*32 + ln)*4 + v;
            g_xAfh[d] = wh; g_xAfl[d] = wl;
        }
    }
}

// ---------------- xproj GEMM: cp.async double-buffered frag pipeline ----------------
__global__ void __launch_bounds__(256,2) k_xproj()
{
    __shared__ unsigned sAh[2][1024], sAl[2][1024], sBh[2][1024], sBl[2][1024];
    int tid = threadIdx.x, lane = tid&31, w = tid>>5, wm = w>>2, wn = w&3;
    int nb0 = blockIdx.x*16, mblk = blockIdx.y;
    float acc[4][4][4];
    #pragma unroll
    for (int i=0;i<4;i++) for (int j=0;j<4;j++) for (int v=0;v<4;v++) acc[i][j][v]=0.f;

    {
        size_t aoff = ((size_t)mblk*4 + 0)*1024;
        size_t boff = ((size_t)0*64 + nb0)*64;
        cpa16(&sAh[0][tid*4], &g_xAfh[aoff + tid*4]);
        cpa16(&sAl[0][tid*4], &g_xAfl[aoff + tid*4]);
        cpa16(&sBh[0][tid*4], &g_WIHfh[boff + tid*4]);
        cpa16(&sBl[0][tid*4], &g_WIHfl[boff + tid*4]);
        CP_COMMIT;
    }
    #pragma unroll 1
    for (int kc = 0; kc < 4; kc++){
        CP_WAIT0;
        __syncthreads();
        if (kc < 3){
            int nb = (kc+1)&1;
            size_t aoff = ((size_t)mblk*4 + kc+1)*1024;
            size_t boff = ((size_t)(kc+1)*64 + nb0)*64;
            cpa16(&sAh[nb][tid*4], &g_xAfh[aoff + tid*4]);
            cpa16(&sAl[nb][tid*4], &g_xAfl[aoff + tid*4]);
            cpa16(&sBh[nb][tid*4], &g_WIHfh[boff + tid*4]);
            cpa16(&sBl[nb][tid*4], &g_WIHfl[boff + tid*4]);
            CP_COMMIT;
        }
        int buf = kc&1;
        uint2 bh[4], bl[4];
        #pragma unroll
        for (int j = 0; j < 4; j++){
            int nt = wn*4 + j;
            bh[j] = *(const uint2*)&sBh[buf][(nt*32+lane)*2];
            bl[j] = *(const uint2*)&sBl[buf][(nt*32+lane)*2];
        }
        #pragma unroll
        for (int i = 0; i < 4; i++){
            int mt = wm*4 + i;
            uint4 ah = *(const uint4*)&sAh[buf][(mt*32+lane)*4];
            uint4 al = *(const uint4*)&sAl[buf][(mt*32+lane)*4];
            #pragma unroll
            for (int j = 0; j < 4; j++){
                mma16(acc[i][j], ah, bh[j]);
                mma16(acc[i][j], ah, bl[j]);
                mma16(acc[i][j], al, bh[j]);
            }
        }
        __syncthreads();
    }
    int g = lane>>2, tc = lane&3;
    int m0 = mblk*128, n0 = blockIdx.x*128;
    #pragma unroll
    for (int i=0;i<4;i++)
      #pragma unroll
      for (int j=0;j<4;j++)
        #pragma unroll
        for (int r2=0;r2<2;r2++){
            int row = m0 + wm*64 + i*16 + g + 8*r2;
            int col = n0 + wn*32 + j*8 + tc*2;
            float2 o = make_float2(acc[i][j][r2*2+0] + g_biasIH[col],
                                   acc[i][j][r2*2+1] + g_biasIH[col+1]);
            *(float2*)&g_xproj[(size_t)row*512 + col] = o;
        }
}

// ---------------- LSTM recurrence ----------------
__global__ void __launch_bounds__(512) k_lstm(const float* __restrict__ whh_f,
                                              const float* __restrict__ whh_b)
{
    __shared__ float hs[2][64][4];
    __shared__ float g_sm[2][4][256];
    int b0  = blockIdx.x * 4;
    int t512 = threadIdx.x;
    int dir = t512 >> 8;
    int tid = t512 & 255;
    const float* whh = dir ? whh_b : whh_f;

    float4 w4[16];
    #pragma unroll
    for (int j4 = 0; j4 < 16; j4++) w4[j4] = *(const float4*)&whh[tid*64 + j4*4];

    hs[dir][tid>>2][tid&3] = 0.f;
    float c = 0.f, hlast = 0.f;

    int tt0 = dir ? 246 : 0;
    float xv[4];
    #pragma unroll
    for (int bi = 0; bi < 4; bi++)
        xv[bi] = g_xproj[((size_t)(b0+bi)*T_ + tt0)*512 + dir*256 + tid];
    __syncthreads();

    for (int s = 0; s < T_; s++){
        u64 acc0 = pack2(xv[0], xv[1]);
        u64 acc1 = pack2(xv[2], xv[3]);

        float xn[4];
        if (s < T_-1){
            int tt2 = dir ? (245 - s) : (s + 1);
            #pragma unroll
            for (int bi = 0; bi < 4; bi++)
                xn[bi] = g_xproj[((size_t)(b0+bi)*T_ + tt2)*512 + dir*256 + tid];
        }

        #pragma unroll
        for (int j4 = 0; j4 < 16; j4++){
            float4 w = w4[j4];
            const ulonglong2* hq = (const ulonglong2*)&hs[dir][j4*4][0];
            ulonglong2 h0 = hq[0];
            ulonglong2 h1 = hq[1];
            ulonglong2 h2 = hq[2];
            ulonglong2 h3 = hq[3];
            u64 wx = pack2(w.x, w.x);
            u64 wy = pack2(w.y, w.y);
            u64 wz = pack2(w.z, w.z);
            u64 ww = pack2(w.w, w.w);
            acc0 = ffma2(wx, h0.x, acc0); acc1 = ffma2(wx, h0.y, acc1);
            acc0 = ffma2(wy, h1.x, acc0); acc1 = ffma2(wy, h1.y, acc1);
            acc0 = ffma2(wz, h2.x, acc0); acc1 = ffma2(wz, h2.y, acc1);
            acc0 = ffma2(ww, h3.x, acc0); acc1 = ffma2(ww, h3.y, acc1);
        }
        float2 f0 = unpack2(acc0), f1 = unpack2(acc1);
        g_sm[dir][0][tid] = f0.x; g_sm[dir][1][tid] = f0.y;
        g_sm[dir][2][tid] = f1.x; g_sm[dir][3][tid] = f1.y;
        __syncthreads();

        int tv = dir ? (246 - s) : s;
        {
            int bi = tid >> 6, j = tid & 63;
            float gi = sigf(g_sm[dir][bi][j]);
            float gf = sigf(g_sm[dir][bi][64+j]);
            float gc = tanhf(g_sm[dir][bi][128+j]);
            float go = sigf(g_sm[dir][bi][192+j]);
            c = gf*c + gi*gc;
            float h = go * tanhf(c);
            hlast = h;
            hs[dir][j][bi] = h;
            g_values[((size_t)(b0+bi)*T_ + tv)*128 + dir*64 + j] = h;
        }
        __syncthreads();
        #pragma unroll
        for (int bi = 0; bi < 4; bi++) xv[bi] = xn[bi];
    }
    {
        int bi = tid >> 6, j = tid & 63;
        g_hT[dir*B_*64 + (b0+bi)*64 + j] = hlast;
    }
}

// ---------------- h_n build + query ----------------
__global__ void k_hnquery(const float* __restrict__ W2b)
{
    __shared__ float hn[128];
    int b = blockIdx.x, j = threadIdx.x;
    int half = j >> 6, jj = j & 63;
    float v;
    if (b < 256) v = g_hT[(2*b + half)*64 + jj];
    else         v = g_hT[B_*64 + (2*(b-256) + half)*64 + jj];
    hn[j] = v;
    __syncthreads();
    float acc = W2b[j];
    #pragma unroll 4
    for (int k = 0; k < 128; k++) acc += hn[k] * g_W2T[k*128 + j];
    g_query[b*128 + j] = acc;
}

// ---------------- keys GEMM + tanh: A smem, B direct ----------------
__global__ void __launch_bounds__(256,2) k_keys(const float* __restrict__ W1b)
{
    __shared__ TSmemA S;
    int tid = threadIdx.x, lane = tid&31, w = tid>>5, wm = w>>2, wn = w&3;
    int m0 = blockIdx.x*128;
    float acc[4][4][4];
    #pragma unroll
    for (int i=0;i<4;i++) for (int j=0;j<4;j++) for (int v=0;v<4;v++) acc[i][j][v]=0.f;

    int mA = tid>>3, kpA = tid&7;

    float2 ra[4];
    {
        #pragma unroll
        for (int r = 0; r < 4; r++)
            ra[r] = *(const float2*)&g_values[(size_t)(m0+mA+32*r)*128 + 2*kpA];
        #pragma unroll
        for (int r = 0; r < 4; r++) astoreB(S.Ah, S.Al, mA+32*r, kpA, ra[r].x, ra[r].y);
    }
    __syncthreads();

    for (int c = 0; c < 8; c++){
        if (c < 7){
            int k0 = (c+1)*16;
            #pragma unroll
            for (int r = 0; r < 4; r++)
                ra[r] = *(const float2*)&g_values[(size_t)(m0+mA+32*r)*128 + k0 + 2*kpA];
        }
        {
            uint2 bh[4], bl[4];
            #pragma unroll
            for (int j = 0; j < 4; j++){
                int nt = wn*4 + j;
                size_t o = (((size_t)c*16 + nt)*32 + lane)*2;
                bh[j] = *(const uint2*)&g_W1fh[o];
                bl[j] = *(const uint2*)&g_W1fl[o];
            }
            #pragma unroll
            for (int i = 0; i < 4; i++){
                int mt = wm*4 + i;
                uint4 ah = *(const uint4*)&S.Ah[mt][lane][0];
                uint4 al = *(const uint4*)&S.Al[mt][lane][0];
                #pragma unroll
                for (int j = 0; j < 4; j++){
                    mma16(acc[i][j], ah, bh[j]);
                    mma16(acc[i][j], ah, bl[j]);
                    mma16(acc[i][j], al, bh[j]);
                }
            }
        }
        __syncthreads();
        if (c < 7){
            #pragma unroll
            for (int r = 0; r < 4; r++) astoreB(S.Ah, S.Al, mA+32*r, kpA, ra[r].x, ra[r].y);
            __syncthreads();
        }
    }
    int g = lane>>2, tc = lane&3;
    #pragma unroll
    for (int i=0;i<4;i++)
      #pragma unroll
      for (int j=0;j<4;j++)
        #pragma unroll
        for (int r2=0;r2<2;r2++){
            int row = m0 + wm*64 + i*16 + g + 8*r2;
            int b = row / T_;
            int t = row - b*T_;
            int col = wn*32 + j*8 + tc*2;
            float e0 = tanhf(acc[i][j][r2*2+0] + W1b[col]   + g_query[b*128 + col]);
            float e1 = tanhf(acc[i][j][r2*2+1] + W1b[col+1] + g_query[b*128 + col+1]);
            unsigned wh, wl; split2(e0, e1, wh, wl);
            int kp = col >> 1, kc = kp>>3, kpA2 = kp&7;
            int mb = t>>7, mloc = t&127;
            int ln = (mloc&7)*4 + (kpA2&3);
            int v = ((kpA2>=4)?2:0) | (((mloc&15)>=8)?1:0);
            size_t d = (((((size_t)b*2 + mb)*8 + kc)*8 + (mloc>>4))*32 + ln)*4 + v;
            g_EAfh[d] = wh; g_EAfl[d] = wl;
        }
}

// ---------------- score GEMM: cp.async double-buffered frag pipeline ----------------
__global__ void __launch_bounds__(256,2) k_scoreK(const float* __restrict__ Vb)
{
    __shared__ unsigned sAh[2][1024], sAl[2][1024], sBh[2][1024], sBl[2][1024];
    int tid = threadIdx.x, lane = tid&31, w = tid>>5, wm = w>>2, wn = w&3;
    int nb0 = blockIdx.x*16, mb = blockIdx.y, b = blockIdx.z;
    float acc[4][4][4];
    #pragma unroll
    for (int i=0;i<4;i++) for (int j=0;j<4;j++) for (int v=0;v<4;v++) acc[i][j][v]=0.f;

    {
        size_t aoff = (((size_t)b*2 + mb)*8 + 0)*1024;
        size_t boff = ((size_t)0*32 + nb0)*64;
        cpa16(&sAh[0][tid*4], &g_EAfh[aoff + tid*4]);
        cpa16(&sAl[0][tid*4], &g_EAfl[aoff + tid*4]);
        cpa16(&sBh[0][tid*4], &g_Vfh[boff + tid*4]);
        cpa16(&sBl[0][tid*4], &g_Vfl[boff + tid*4]);
        CP_COMMIT;
    }
    #pragma unroll 1
    for (int kc = 0; kc < 8; kc++){
        CP_WAIT0;
        __syncthreads();
        if (kc < 7){
            int nb = (kc+1)&1;
            size_t aoff = (((size_t)b*2 + mb)*8 + kc+1)*1024;
            size_t boff = ((size_t)(kc+1)*32 + nb0)*64;
            cpa16(&sAh[nb][tid*4], &g_EAfh[aoff + tid*4]);
            cpa16(&sAl[nb][tid*4], &g_EAfl[aoff + tid*4]);
            cpa16(&sBh[nb][tid*4], &g_Vfh[boff + tid*4]);
            cpa16(&sBl[nb][tid*4], &g_Vfl[boff + tid*4]);
            CP_COMMIT;
        }
        int buf = kc&1;
        uint2 bh[4], bl[4];
        #pragma unroll
        for (int j = 0; j < 4; j++){
            int nt = wn*4 + j;
            bh[j] = *(const uint2*)&sBh[buf][(nt*32+lane)*2];
            bl[j] = *(const uint2*)&sBl[buf][(nt*32+lane)*2];
        }
        #pragma unroll
        for (int i = 0; i < 4; i++){
            int mt = wm*4 + i;
            uint4 ah = *(const uint4*)&sAh[buf][(mt*32+lane)*4];
            uint4 al = *(const uint4*)&sAl[buf][(mt*32+lane)*4];
            #pragma unroll
            for (int j = 0; j < 4; j++){
                mma16(acc[i][j], ah, bh[j]);
                mma16(acc[i][j], ah, bl[j]);
                mma16(acc[i][j], al, bh[j]);
            }
        }
        __syncthreads();
    }
    int g = lane>>2, tc = lane&3;
    int m0 = mb*128, n0 = blockIdx.x*128;
    #pragma unroll
    for (int i=0;i<4;i++)
      #pragma unroll
      for (int j=0;j<4;j++)
        #pragma unroll
        for (int r2=0;r2<2;r2++){
            int row = m0 + wm*64 + i*16 + g + 8*r2;
            int col = n0 + wn*32 + j*8 + tc*2;
            if (row < T_ && col < NTF_){
                float2 o = make_float2(acc[i][j][r2*2+0] + Vb[col],
                                       acc[i][j][r2*2+1] + Vb[col+1]);
                *(float2*)&g_score[((size_t)b*T_ + row)*NTF_ + col] = o;
            }
        }
}

// ---------------- softmax over time ----------------
__global__ void k_softmax()
{
    int b = blockIdx.x, k = threadIdx.x;
    if (k >= NTF_) return;
    float* base = g_score + (size_t)b*T_*NTF_ + k;
    float m = -FLT_MAX, s = 0.f;
    for (int t = 0; t < T_; t++){
        float x = base[t*NTF_];
        if (x > m){ s = s*__expf(m - x) + 1.f; m = x; }
        else s += __expf(x - m);
    }
    float inv = 1.f / s;
    for (int t = 0; t < T_; t++){
        float x = base[t*NTF_];
        base[t*NTF_] = __expf(x - m) * inv;
    }
}

// ---------------- context GEMM (full smem, single buffer) ----------------
__global__ void __launch_bounds__(256,2) k_context()
{
    __shared__ TSmem S;
    int tid = threadIdx.x, lane = tid&31, w = tid>>5, wm = w>>2, wn = w&3;
    int m0 = blockIdx.x*128, b = blockIdx.y;
    float acc[4][4][4];
    #pragma unroll
    for (int i=0;i<4;i++) for (int j=0;j<4;j++) for (int v=0;v<4;v++) acc[i][j][v]=0.f;

    int kpB = tid>>5, mB = tid&31;

    float ax0[4], ax1[4], bx0[4], bx1[4];
    {
        #pragma unroll
        for (int r = 0; r < 4; r++){
            int m = mB + 32*r;
            bool okm = (m0+m < NTF_);
            int t0 = 2*kpB, t1 = 2*kpB+1;
            ax0[r] = (okm && t0 < T_) ? g_score[((size_t)b*T_ + t0)*NTF_ + m0+m] : 0.f;
            ax1[r] = (okm && t1 < T_) ? g_score[((size_t)b*T_ + t1)*NTF_ + m0+m] : 0.f;
            bx0[r] = (t0 < T_) ? g_values[((size_t)b*T_ + t0)*128 + m] : 0.f;
            bx1[r] = (t1 < T_) ? g_values[((size_t)b*T_ + t1)*128 + m] : 0.f;
        }
        #pragma unroll
        for (int r = 0; r < 4; r++){
            astoreB(S.Ah, S.Al, mB+32*r, kpB, ax0[r], ax1[r]);
            bstoreB(&S.Bh[0][0][0], &S.Bl[0][0][0], kpB, mB+32*r, bx0[r], bx1[r]);
        }
    }
    __syncthreads();

    for (int c = 0; c < 16; c++){
        if (c < 15){
            int k0 = (c+1)*16;
            #pragma unroll
            for (int r = 0; r < 4; r++){
                int m = mB + 32*r;
                bool okm = (m0+m < NTF_);
                int t0 = k0 + 2*kpB, t1 = t0 + 1;
                ax0[r] = (okm && t0 < T_) ? g_score[((size_t)b*T_ + t0)*NTF_ + m0+m] : 0.f;
                ax1[r] = (okm && t1 < T_) ? g_score[((size_t)b*T_ + t1)*NTF_ + m0+m] : 0.f;
                bx0[r] = (t0 < T_) ? g_values[((size_t)b*T_ + t0)*128 + m] : 0.f;
                bx1[r] = (t1 < T_) ? g_values[((size_t)b*T_ + t1)*128 + m] : 0.f;
            }
        }
        tcomp(S, acc, lane, wm, wn);
        __syncthreads();
        if (c < 15){
            #pragma unroll
            for (int r = 0; r < 4; r++){
                astoreB(S.Ah, S.Al, mB+32*r, kpB, ax0[r], ax1[r]);
                bstoreB(&S.Bh[0][0][0], &S.Bl[0][0][0], kpB, mB+32*r, bx0[r], bx1[r]);
            }
            __syncthreads();
        }
    }
    int g = lane>>2, tc = lane&3;
    #pragma unroll
    for (int i=0;i<4;i++)
      #pragma unroll
      for (int j=0;j<4;j++)
        #pragma unroll
        for (int r2=0;r2<2;r2++){
            int row = m0 + wm*64 + i*16 + g + 8*r2;
            int col = wn*32 + j*8 + tc*2;
            if (row < NTF_){
                float2 o = make_float2(acc[i][j][r2*2+0], acc[i][j][r2*2+1]);
                *(float2*)&g_ctx[((size_t)b*NTF_ + row)*128 + col] = o;
            }
        }
}

// ---------------- per-TF heads ----------------
__global__ void __launch_bounds__(256) k_heads(
    const float* __restrict__ fc1w, const float* __restrict__ fc1b,
    const float* __restrict__ fc2w, const float* __restrict__ fc2b,
    float* __restrict__ out)
{
    __shared__ float fw[128][65];
    __shared__ float cs[16][128];
    __shared__ float red[16][65];
    int tid = threadIdx.x;
    int b0 = blockIdx.x*16, k = blockIdx.y;

    for (int i = tid; i < 8192; i += 256){
        int o = i >> 7, d = i & 127;
        fw[d][o] = fc1w[(size_t)k*8192 + i];
    }
    for (int i = tid; i < 2048; i += 256){
        int bi = i >> 7, d = i & 127;
        cs[bi][d] = g_ctx[((size_t)(b0+bi)*NTF_ + k)*128 + d];
    }
    __syncthreads();

    int o = tid & 63;
    float f1b = fc1b[k*64 + o];
    float f2w = fc2w[k*64 + o];
    #pragma unroll
    for (int p = 0; p < 4; p++){
        int bi = (tid >> 6) + p*4;
        float acc = 0.f;
        #pragma unroll
        for (int d4 = 0; d4 < 32; d4++){
            float4 cv = *(const float4*)&cs[bi][d4*4];
            acc += fw[d4*4+0][o]*cv.x + fw[d4*4+1][o]*cv.y
                 + fw[d4*4+2][o]*cv.z + fw[d4*4+3][o]*cv.w;
        }
        float h1 = fmaxf(acc + f1b, 0.f);
        red[bi][o] = h1 * f2w;
    }
    __syncthreads();
    if (tid < 16){
        float s = fc2b[k];
        #pragma unroll 8
        for (int oo = 0; oo < 64; oo++) s += red[tid][oo];
        out[(size_t)(b0 + tid)*NTF_ + k] = s;
    }
}

// ---------------- launch ----------------
extern "C" void kernel_launch(void* const* d_in, const int* in_sizes, int n_in,
                              void* d_out, int out_size)
{
    const float* DNA    = (const float*)d_in[0];
    const float* c0w    = (const float*)d_in[1];
    const float* c0b    = (const float*)d_in[2];
    const float* bn0g   = (const float*)d_in[3];
    const float* bn0b   = (const float*)d_in[4];
    const float* bn0m   = (const float*)d_in[5];
    const float* bn0v   = (const float*)d_in[6];
    const float* c1w    = (const float*)d_in[7];
    const float* c1b    = (const float*)d_in[8];
    const float* bn1g   = (const float*)d_in[9];
    const float* bn1b   = (const float*)d_in[10];
    const float* bn1m   = (const float*)d_in[11];
    const float* bn1v   = (const float*)d_in[12];
    const float* wih_f  = (const float*)d_in[13];
    const float* whh_f  = (const float*)d_in[14];
    const float* bih_f  = (const float*)d_in[15];
    const float* bhh_f  = (const float*)d_in[16];
    const float* wih_b  = (const float*)d_in[17];
    const float* whh_b  = (const float*)d_in[18];
    const float* bih_b  = (const float*)d_in[19];
    const float* bhh_b  = (const float*)d_in[20];
    const float* W1w    = (const float*)d_in[21];
    const float* W1b    = (const float*)d_in[22];
    const float* W2w    = (const float*)d_in[23];
    const float* W2b    = (const float*)d_in[24];
    const float* Vw     = (const float*)d_in[25];
    const float* Vb     = (const float*)d_in[26];
    const float* fc1w   = (const float*)d_in[27];
    const float* fc1b   = (const float*)d_in[28];
    const float* fc2w   = (const float*)d_in[29];
    const float* fc2b   = (const float*)d_in[30];
    float* out = (float*)d_out;

    k_prep<<<512, 256>>>(W1w, W2w, Vw, wih_f, wih_b, bih_f, bhh_f, bih_b, bhh_b, c1w);
    k_conv0<<<512, 256>>>(DNA, c0w, c0b, bn0g, bn0b, bn0m, bn0v);
    k_conv1<<<988, 256>>>(c1b, bn1g, bn1b, bn1m, bn1v);
    k_xproj<<<dim3(4, 988), 256>>>();
    k_lstm<<<128, 512>>>(whh_f, whh_b);
    k_hnquery<<<512, 128>>>(W2b);
    k_keys<<<988, 256>>>(W1b);
    k_scoreK<<<dim3(2, 2, 512), 256>>>(Vb);
    k_softmax<<<512, 256>>>();
    k_context<<<dim3(2, 512), 256>>>();
    k_heads<<<dim3(32, 200), 256>>>(fc1w, fc1b, fc2w, fc2b, out);
}

// round 16
// speedup vs baseline: 1.1665x; 1.1665x over previous
#include <cuda_runtime.h>
#include <cuda_bf16.h>
#include <math.h>
#include <float.h>

#define B_    512
#define T_    247
#define C_    64
#define NTF_  200
#define LPOOL 254
#define MROWS (B_*T_)      // 126464
#define MBLK  988          // MROWS/128

typedef unsigned long long u64;

// ---------------- scratch ----------------
__device__ float g_pooled[B_*C_*LPOOL];
__device__ float g_xproj [(size_t)MROWS*512];
__device__ float g_values[MROWS*128];
__device__ float g_hT    [2*B_*64];
__device__ float g_query [B_*128];
__device__ float g_score [MROWS*NTF_];
__device__ float g_ctx   [B_*NTF_*128];
__device__ float g_W2T [128*128];
__device__ float g_biasIH[512];
// fragment-ordered operand arrays (hi / lo bf16x2 words)
__device__ unsigned g_xAfh[(size_t)MBLK*4*8*32*4], g_xAfl[(size_t)MBLK*4*8*32*4];
__device__ unsigned g_EAfh[(size_t)B_*2*8*8*32*4], g_EAfl[(size_t)B_*2*8*8*32*4];
__device__ unsigned g_WIHfh[4*64*32*2],  g_WIHfl[4*64*32*2];
__device__ unsigned g_W1fh [8*16*32*2],  g_W1fl [8*16*32*2];
__device__ unsigned g_Vfh  [8*32*32*2],  g_Vfl  [8*32*32*2];
__device__ unsigned g_c1fh [32*8*32*2],  g_c1fl [32*8*32*2];

__device__ __forceinline__ float sigf(float x){ return 1.f/(1.f+__expf(-x)); }

// ---- packed fp32x2 helpers (FFMA2) — lstm ----
__device__ __forceinline__ u64 ffma2(u64 a, u64 b, u64 c){
    u64 d;
    asm("fma.rn.f32x2 %0, %1, %2, %3;" : "=l"(d) : "l"(a), "l"(b), "l"(c));
    return d;
}
__device__ __forceinline__ u64 pack2(float x, float y){
    u64 d;
    asm("mov.b64 %0, {%1, %2};" : "=l"(d) : "f"(x), "f"(y));
    return d;
}
__device__ __forceinline__ float2 unpack2(u64 d){
    float2 f;
    asm("mov.b64 {%0, %1}, %2;" : "=f"(f.x), "=f"(f.y) : "l"(d));
    return f;
}

// ---- bf16 2-term split ----
__device__ __forceinline__ void split2(float x0, float x1, unsigned &wh, unsigned &wl){
    unsigned hh;
    asm("cvt.rn.bf16x2.f32 %0, %1, %2;" : "=r"(hh) : "f"(x1), "f"(x0));
    float h0 = __uint_as_float(hh << 16);
    float h1 = __uint_as_float(hh & 0xffff0000u);
    float r0 = x0 - h0, r1 = x1 - h1;
    asm("cvt.rn.bf16x2.f32 %0, %1, %2;" : "=r"(wl) : "f"(r1), "f"(r0));
    wh = hh;
}
__device__ __forceinline__ void mma16(float *d, const uint4 &a, const uint2 &b){
    asm volatile("mma.sync.aligned.m16n8k16.row.col.f32.bf16.bf16.f32 "
        "{%0,%1,%2,%3}, {%4,%5,%6,%7}, {%8,%9}, {%0,%1,%2,%3};"
        : "+f"(d[0]), "+f"(d[1]), "+f"(d[2]), "+f"(d[3])
        : "r"(a.x), "r"(a.y), "r"(a.z), "r"(a.w), "r"(b.x), "r"(b.y));
}

// ---- cp.async helpers ----
__device__ __forceinline__ void cpa16(void *smem, const void *gmem){
    unsigned s = (unsigned)__cvta_generic_to_shared(smem);
    asm volatile("cp.async.cg.shared.global [%0], [%1], 16;" :: "r"(s), "l"(gmem));
}
#define CP_COMMIT asm volatile("cp.async.commit_group;" ::: "memory")
#define CP_WAIT0  asm volatile("cp.async.wait_group 0;" ::: "memory")

// smem fragment tiles
struct TSmemA { unsigned Ah[8][32][4], Al[8][32][4]; };
struct TSmem  {
    unsigned Ah[8][32][4], Al[8][32][4];
    unsigned Bh[16][33][2], Bl[16][33][2];
};

__device__ __forceinline__ void astoreW(unsigned (&Ah)[8][32][4], unsigned (&Al)[8][32][4],
                                        int m, int kp, unsigned wh, unsigned wl){
    int mt = m>>4, t = (m&7)*4 + (kp&3);
    int v = ((kp>=4)?2:0) | (((m&15)>=8)?1:0);
    Ah[mt][t][v] = wh; Al[mt][t][v] = wl;
}
__device__ __forceinline__ void bstoreW(unsigned *Bh, unsigned *Bl,
                                        int kp, int n, unsigned wh, unsigned wl){
    int idx = (n>>3)*66 + ((n&7)*4 + (kp&3))*2 + ((kp>=4)?1:0);
    Bh[idx] = wh; Bl[idx] = wl;
}
__device__ __forceinline__ void astoreB(unsigned (&Ah)[8][32][4], unsigned (&Al)[8][32][4],
                                        int m, int kp, float x0, float x1){
    unsigned wh, wl; split2(x0, x1, wh, wl);
    astoreW(Ah, Al, m, kp, wh, wl);
}
__device__ __forceinline__ void bstoreB(unsigned *Bh, unsigned *Bl,
                                        int kp, int n, float x0, float x1){
    unsigned wh, wl; split2(x0, x1, wh, wl);
    bstoreW(Bh, Bl, kp, n, wh, wl);
}

__device__ __forceinline__ void tcomp(const TSmem &S, float (&acc)[4][4][4],
                                      int lane, int wm, int wn)
{
    uint2 bh[4], bl[4];
    #pragma unroll
    for (int j = 0; j < 4; j++){
        int nt = wn*4 + j;
        bh[j] = *(const uint2*)&S.Bh[nt][lane][0];
        bl[j] = *(const uint2*)&S.Bl[nt][lane][0];
    }
    #pragma unroll
    for (int i = 0; i < 4; i++){
        int mt = wm*4 + i;
        uint4 ah = *(const uint4*)&S.Ah[mt][lane][0];
        uint4 al = *(const uint4*)&S.Al[mt][lane][0];
        #pragma unroll
        for (int j = 0; j < 4; j++){
            mma16(acc[i][j], ah, bh[j]);
            mma16(acc[i][j], ah, bl[j]);
            mma16(acc[i][j], al, bh[j]);
        }
    }
}

// ---------------- prep ----------------
__global__ void k_prep(const float* __restrict__ W1, const float* __restrict__ W2,
                       const float* __restrict__ V,
                       const float* __restrict__ wih_f, const float* __restrict__ wih_b,
                       const float* __restrict__ bih_f, const float* __restrict__ bhh_f,
                       const float* __restrict__ bih_b, const float* __restrict__ bhh_b,
                       const float* __restrict__ c1w)
{
    int idx = blockIdx.x*blockDim.x + threadIdx.x;
    if (idx < 16384){ int n = idx/128, k = idx%128; g_W2T[k*128+n] = W2[idx]; }
    if (idx < 16384){
        int kp = idx >> 9, n = idx & 511;
        float x0 = (n<256)? wih_f[n*64 + 2*kp]   : wih_b[(n-256)*64 + 2*kp];
        float x1 = (n<256)? wih_f[n*64 + 2*kp+1] : wih_b[(n-256)*64 + 2*kp+1];
        unsigned wh, wl; split2(x0, x1, wh, wl);
        int kc = kp>>3, kpA = kp&7;
        int lane = (n&7)*4 + (kpA&3), v = (kpA>=4)?1:0;
        int d = (((kc*64 + (n>>3))*32 + lane)*2) + v;
        g_WIHfh[d] = wh; g_WIHfl[d] = wl;
    }
    if (idx < 8192){
        int kp = idx >> 7, n = idx & 127;
        unsigned wh, wl; split2(W1[n*128+2*kp], W1[n*128+2*kp+1], wh, wl);
        int kc = kp>>3, kpA = kp&7;
        int lane = (n&7)*4 + (kpA&3), v = (kpA>=4)?1:0;
        int d = (((kc*16 + (n>>3))*32 + lane)*2) + v;
        g_W1fh[d] = wh; g_W1fl[d] = wl;
    }
    if (idx < 64*NTF_){
        int kp = idx / NTF_, n = idx % NTF_;
        unsigned wh, wl; split2(V[n*128+2*kp], V[n*128+2*kp+1], wh, wl);
        int kc = kp>>3, kpA = kp&7;
        int lane = (n&7)*4 + (kpA&3), v = (kpA>=4)?1:0;
        int d = (((kc*32 + (n>>3))*32 + lane)*2) + v;
        g_Vfh[d] = wh; g_Vfl[d] = wl;
    }
    if (idx < 16384){
        int kp = idx >> 6, n = idx & 63;
        unsigned wh, wl; split2(c1w[n*512+2*kp], c1w[n*512+2*kp+1], wh, wl);
        int kc = kp>>3, kpA = kp&7;
        int lane = (n&7)*4 + (kpA&3), v = (kpA>=4)?1:0;
        int d = (((kc*8 + (n>>3))*32 + lane)*2) + v;
        g_c1fh[d] = wh; g_c1fl[d] = wl;
    }
    if (idx < 512){ g_biasIH[idx] = (idx < 256) ? (bih_f[idx] + bhh_f[idx])
                                                : (bih_b[idx-256] + bhh_b[idx-256]); }
}

// ---------------- conv0 ----------------
__global__ void __launch_bounds__(256) k_conv0(
    const float* __restrict__ x, const float* __restrict__ w, const float* __restrict__ cb,
    const float* __restrict__ g, const float* __restrict__ bb,
    const float* __restrict__ mm, const float* __restrict__ vv)
{
    __shared__ float4 xs4[1024];
    int b = blockIdx.x, tid = threadIdx.x;
    const float4* in4 = (const float4*)(x + (size_t)b*4096);
    for (int i = tid; i < 1024; i += 256) xs4[i] = in4[i];

    int c = tid & 63;
    float4 wr[8];
    #pragma unroll
    for (int kk = 0; kk < 8; kk++)
        wr[kk] = make_float4(w[c*32 + 0*8 + kk], w[c*32 + 1*8 + kk],
                             w[c*32 + 2*8 + kk], w[c*32 + 3*8 + kk]);
    float scale = g[c] * rsqrtf(vv[c] + 1e-5f);
    float shift = bb[c] - mm[c]*scale;
    float cbc   = cb[c];
    __syncthreads();

    for (int idx = tid; idx < 64*LPOOL; idx += 256){
        int q = idx >> 6;
        float best = -FLT_MAX;
        #pragma unroll
        for (int dp = 0; dp < 4; dp++){
            int p = 4*q + dp;
            float acc = cbc;
            #pragma unroll
            for (int kk = 0; kk < 8; kk++){
                float4 xv = xs4[p+kk];
                acc += wr[kk].x*xv.x + wr[kk].y*xv.y + wr[kk].z*xv.z + wr[kk].w*xv.w;
            }
            best = fmaxf(best, acc*scale + shift);
        }
        g_pooled[(b*64 + c)*LPOOL + q] = fmaxf(best, 0.f);
    }
}

// ---------------- conv1 GEMM: A smem, B direct frag LDG ----------------
__global__ void __launch_bounds__(256,2) k_conv1(
    const float* __restrict__ cb,
    const float* __restrict__ gg, const float* __restrict__ bb,
    const float* __restrict__ mm, const float* __restrict__ vv)
{
    __shared__ TSmemA S;
    int tid = threadIdx.x, lane = tid&31, w = tid>>5;
    int m0  = blockIdx.x*128;
    float acc[8][4];
    #pragma unroll
    for (int j=0;j<8;j++) for (int v=0;v<4;v++) acc[j][v]=0.f;

    int mA = tid>>3, kpA = tid&7;
    int bz[4], tl[4];
    #pragma unroll
    for (int r = 0; r < 4; r++){
        int gm = m0 + mA + 32*r;
        bz[r] = gm / T_;
        tl[r] = gm - bz[r]*T_;
    }

    float ax0[4], ax1[4];
    {
        int k = 2*kpA;
        #pragma unroll
        for (int r = 0; r < 4; r++){
            int base = (bz[r]*64 + (k>>3))*LPOOL + tl[r] + (k&7);
            ax0[r] = g_pooled[base]; ax1[r] = g_pooled[base+1];
        }
        #pragma unroll
        for (int r = 0; r < 4; r++) astoreB(S.Ah, S.Al, mA+32*r, kpA, ax0[r], ax1[r]);
    }
    __syncthreads();

    for (int c = 0; c < 32; c++){
        if (c < 31){
            int k = (c+1)*16 + 2*kpA;
            #pragma unroll
            for (int r = 0; r < 4; r++){
                int base = (bz[r]*64 + (k>>3))*LPOOL + tl[r] + (k&7);
                ax0[r] = g_pooled[base]; ax1[r] = g_pooled[base+1];
            }
        }
        {
            uint4 ah = *(const uint4*)&S.Ah[w][lane][0];
            uint4 al = *(const uint4*)&S.Al[w][lane][0];
            #pragma unroll
            for (int j = 0; j < 8; j++){
                size_t o = (((size_t)c*8 + j)*32 + lane)*2;
                uint2 bh = *(const uint2*)&g_c1fh[o];
                uint2 bl = *(const uint2*)&g_c1fl[o];
                mma16(acc[j], ah, bh);
                mma16(acc[j], ah, bl);
                mma16(acc[j], al, bh);
            }
        }
        __syncthreads();
        if (c < 31){
            #pragma unroll
            for (int r = 0; r < 4; r++) astoreB(S.Ah, S.Al, mA+32*r, kpA, ax0[r], ax1[r]);
            __syncthreads();
        }
    }
    int g = lane>>2, tc = lane&3;
    #pragma unroll
    for (int j = 0; j < 8; j++){
        #pragma unroll
        for (int r2 = 0; r2 < 2; r2++){
            int row = m0 + w*16 + g + 8*r2;
            int col = j*8 + tc*2;
            float s0 = gg[col]   * rsqrtf(vv[col]   + 1e-5f);
            float s1 = gg[col+1] * rsqrtf(vv[col+1] + 1e-5f);
            float v0 = fmaxf(acc[j][r2*2+0]*s0 + bb[col]   + (cb[col]  -mm[col])  *s0, 0.f);
            float v1 = fmaxf(acc[j][r2*2+1]*s1 + bb[col+1] + (cb[col+1]-mm[col+1])*s1, 0.f);
            unsigned wh, wl; split2(v0, v1, wh, wl);
            int kp = col >> 1, kc = kp>>3, kpA2 = kp&7;
            int mblk = row>>7, mloc = row&127;
            int ln = (mloc&7)*4 + (kpA2&3);
            int v = ((kpA2>=4)?2:0) | (((mloc&15)>=8)?1:0);
            size_t d = ((((size_t)mblk*4 + kc)*8 + (mloc>>4))*32 + ln)*4 + v;
            g_xAfh[d] = wh; g_xAfl[d] = wl;
        }
    }
}

// ---------------- xproj GEMM: cp.async double-buffered frag pipeline ----------------
__global__ void __launch_bounds__(256,2) k_xproj()
{
    __shared__ unsigned sAh[2][1024], sAl[2][1024], sBh[2][1024], sBl[2][1024];
    int tid = threadIdx.x, lane = tid&31, w = tid>>5, wm = w>>2, wn = w&3;
    int nb0 = blockIdx.x*16, mblk = blockIdx.y;
    float acc[4][4][4];
    #pragma unroll
    for (int i=0;i<4;i++) for (int j=0;j<4;j++) for (int v=0;v<4;v++) acc[i][j][v]=0.f;

    {
        size_t aoff = ((size_t)mblk*4 + 0)*1024;
        size_t boff = ((size_t)0*64 + nb0)*64;
        cpa16(&sAh[0][tid*4], &g_xAfh[aoff + tid*4]);
        cpa16(&sAl[0][tid*4], &g_xAfl[aoff + tid*4]);
        cpa16(&sBh[0][tid*4], &g_WIHfh[boff + tid*4]);
        cpa16(&sBl[0][tid*4], &g_WIHfl[boff + tid*4]);
        CP_COMMIT;
    }
    #pragma unroll 1
    for (int kc = 0; kc < 4; kc++){
        CP_WAIT0;
        __syncthreads();
        if (kc < 3){
            int nb = (kc+1)&1;
            size_t aoff = ((size_t)mblk*4 + kc+1)*1024;
            size_t boff = ((size_t)(kc+1)*64 + nb0)*64;
            cpa16(&sAh[nb][tid*4], &g_xAfh[aoff + tid*4]);
            cpa16(&sAl[nb][tid*4], &g_xAfl[aoff + tid*4]);
            cpa16(&sBh[nb][tid*4], &g_WIHfh[boff + tid*4]);
            cpa16(&sBl[nb][tid*4], &g_WIHfl[boff + tid*4]);
            CP_COMMIT;
        }
        int buf = kc&1;
        uint2 bh[4], bl[4];
        #pragma unroll
        for (int j = 0; j < 4; j++){
            int nt = wn*4 + j;
            bh[j] = *(const uint2*)&sBh[buf][(nt*32+lane)*2];
            bl[j] = *(const uint2*)&sBl[buf][(nt*32+lane)*2];
        }
        #pragma unroll
        for (int i = 0; i < 4; i++){
            int mt = wm*4 + i;
            uint4 ah = *(const uint4*)&sAh[buf][(mt*32+lane)*4];
            uint4 al = *(const uint4*)&sAl[buf][(mt*32+lane)*4];
            #pragma unroll
            for (int j = 0; j < 4; j++){
                mma16(acc[i][j], ah, bh[j]);
                mma16(acc[i][j], ah, bl[j]);
                mma16(acc[i][j], al, bh[j]);
            }
        }
        __syncthreads();
    }
    int g = lane>>2, tc = lane&3;
    int m0 = mblk*128, n0 = blockIdx.x*128;
    #pragma unroll
    for (int i=0;i<4;i++)
      #pragma unroll
      for (int j=0;j<4;j++)
        #pragma unroll
        for (int r2=0;r2<2;r2++){
            int row = m0 + wm*64 + i*16 + g + 8*r2;
            int col = n0 + wn*32 + j*8 + tc*2;
            float2 o = make_float2(acc[i][j][r2*2+0] + g_biasIH[col],
                                   acc[i][j][r2*2+1] + g_biasIH[col+1]);
            *(float2*)&g_xproj[(size_t)row*512 + col] = o;
        }
}

// ---------------- LSTM recurrence ----------------
__global__ void __launch_bounds__(512) k_lstm(const float* __restrict__ whh_f,
                                              const float* __restrict__ whh_b)
{
    __shared__ float hs[2][64][4];
    __shared__ float g_sm[2][4][256];
    int b0  = blockIdx.x * 4;
    int t512 = threadIdx.x;
    int dir = t512 >> 8;
    int tid = t512 & 255;
    const float* whh = dir ? whh_b : whh_f;

    float4 w4[16];
    #pragma unroll
    for (int j4 = 0; j4 < 16; j4++) w4[j4] = *(const float4*)&whh[tid*64 + j4*4];

    hs[dir][tid>>2][tid&3] = 0.f;
    float c = 0.f, hlast = 0.f;

    int tt0 = dir ? 246 : 0;
    float xv[4];
    #pragma unroll
    for (int bi = 0; bi < 4; bi++)
        xv[bi] = g_xproj[((size_t)(b0+bi)*T_ + tt0)*512 + dir*256 + tid];
    __syncthreads();

    for (int s = 0; s < T_; s++){
        u64 acc0 = pack2(xv[0], xv[1]);
        u64 acc1 = pack2(xv[2], xv[3]);

        float xn[4];
        if (s < T_-1){
            int tt2 = dir ? (245 - s) : (s + 1);
            #pragma unroll
            for (int bi = 0; bi < 4; bi++)
                xn[bi] = g_xproj[((size_t)(b0+bi)*T_ + tt2)*512 + dir*256 + tid];
        }

        #pragma unroll
        for (int j4 = 0; j4 < 16; j4++){
            float4 w = w4[j4];
            const ulonglong2* hq = (const ulonglong2*)&hs[dir][j4*4][0];
            ulonglong2 h0 = hq[0];
            ulonglong2 h1 = hq[1];
            ulonglong2 h2 = hq[2];
            ulonglong2 h3 = hq[3];
            u64 wx = pack2(w.x, w.x);
            u64 wy = pack2(w.y, w.y);
            u64 wz = pack2(w.z, w.z);
            u64 ww = pack2(w.w, w.w);
            acc0 = ffma2(wx, h0.x, acc0); acc1 = ffma2(wx, h0.y, acc1);
            acc0 = ffma2(wy, h1.x, acc0); acc1 = ffma2(wy, h1.y, acc1);
            acc0 = ffma2(wz, h2.x, acc0); acc1 = ffma2(wz, h2.y, acc1);
            acc0 = ffma2(ww, h3.x, acc0); acc1 = ffma2(ww, h3.y, acc1);
        }
        float2 f0 = unpack2(acc0), f1 = unpack2(acc1);
        g_sm[dir][0][tid] = f0.x; g_sm[dir][1][tid] = f0.y;
        g_sm[dir][2][tid] = f1.x; g_sm[dir][3][tid] = f1.y;
        __syncthreads();

        int tv = dir ? (246 - s) : s;
        {
            int bi = tid >> 6, j = tid & 63;
            float gi = sigf(g_sm[dir][bi][j]);
            float gf = sigf(g_sm[dir][bi][64+j]);
            float gc = tanhf(g_sm[dir][bi][128+j]);
            float go = sigf(g_sm[dir][bi][192+j]);
            c = gf*c + gi*gc;
            float h = go * tanhf(c);
            hlast = h;
            hs[dir][j][bi] = h;
            g_values[((size_t)(b0+bi)*T_ + tv)*128 + dir*64 + j] = h;
        }
        __syncthreads();
        #pragma unroll
        for (int bi = 0; bi < 4; bi++) xv[bi] = xn[bi];
    }
    {
        int bi = tid >> 6, j = tid & 63;
        g_hT[dir*B_*64 + (b0+bi)*64 + j] = hlast;
    }
}

// ---------------- h_n build + query ----------------
__global__ void k_hnquery(const float* __restrict__ W2b)
{
    __shared__ float hn[128];
    int b = blockIdx.x, j = threadIdx.x;
    int half = j >> 6, jj = j & 63;
    float v;
    if (b < 256) v = g_hT[(2*b + half)*64 + jj];
    else         v = g_hT[B_*64 + (2*(b-256) + half)*64 + jj];
    hn[j] = v;
    __syncthreads();
    float acc = W2b[j];
    #pragma unroll 4
    for (int k = 0; k < 128; k++) acc += hn[k] * g_W2T[k*128 + j];
    g_query[b*128 + j] = acc;
}

// ---------------- keys GEMM + tanh: A smem, B direct ----------------
__global__ void __launch_bounds__(256,2) k_keys(const float* __restrict__ W1b)
{
    __shared__ TSmemA S;
    int tid = threadIdx.x, lane = tid&31, w = tid>>5, wm = w>>2, wn = w&3;
    int m0 = blockIdx.x*128;
    float acc[4][4][4];
    #pragma unroll
    for (int i=0;i<4;i++) for (int j=0;j<4;j++) for (int v=0;v<4;v++) acc[i][j][v]=0.f;

    int mA = tid>>3, kpA = tid&7;

    float2 ra[4];
    {
        #pragma unroll
        for (int r = 0; r < 4; r++)
            ra[r] = *(const float2*)&g_values[(size_t)(m0+mA+32*r)*128 + 2*kpA];
        #pragma unroll
        for (int r = 0; r < 4; r++) astoreB(S.Ah, S.Al, mA+32*r, kpA, ra[r].x, ra[r].y);
    }
    __syncthreads();

    for (int c = 0; c < 8; c++){
        if (c < 7){
            int k0 = (c+1)*16;
            #pragma unroll
            for (int r = 0; r < 4; r++)
                ra[r] = *(const float2*)&g_values[(size_t)(m0+mA+32*r)*128 + k0 + 2*kpA];
        }
        {
            uint2 bh[4], bl[4];
            #pragma unroll
            for (int j = 0; j < 4; j++){
                int nt = wn*4 + j;
                size_t o = (((size_t)c*16 + nt)*32 + lane)*2;
                bh[j] = *(const uint2*)&g_W1fh[o];
                bl[j] = *(const uint2*)&g_W1fl[o];
            }
            #pragma unroll
            for (int i = 0; i < 4; i++){
                int mt = wm*4 + i;
                uint4 ah = *(const uint4*)&S.Ah[mt][lane][0];
                uint4 al = *(const uint4*)&S.Al[mt][lane][0];
                #pragma unroll
                for (int j = 0; j < 4; j++){
                    mma16(acc[i][j], ah, bh[j]);
                    mma16(acc[i][j], ah, bl[j]);
                    mma16(acc[i][j], al, bh[j]);
                }
            }
        }
        __syncthreads();
        if (c < 7){
            #pragma unroll
            for (int r = 0; r < 4; r++) astoreB(S.Ah, S.Al, mA+32*r, kpA, ra[r].x, ra[r].y);
            __syncthreads();
        }
    }
    int g = lane>>2, tc = lane&3;
    #pragma unroll
    for (int i=0;i<4;i++)
      #pragma unroll
      for (int j=0;j<4;j++)
        #pragma unroll
        for (int r2=0;r2<2;r2++){
            int row = m0 + wm*64 + i*16 + g + 8*r2;
            int b = row / T_;
            int t = row - b*T_;
            int col = wn*32 + j*8 + tc*2;
            float e0 = tanhf(acc[i][j][r2*2+0] + W1b[col]   + g_query[b*128 + col]);
            float e1 = tanhf(acc[i][j][r2*2+1] + W1b[col+1] + g_query[b*128 + col+1]);
            unsigned wh, wl; split2(e0, e1, wh, wl);
            int kp = col >> 1, kc = kp>>3, kpA2 = kp&7;
            int mb = t>>7, mloc = t&127;
            int ln = (mloc&7)*4 + (kpA2&3);
            int v = ((kpA2>=4)?2:0) | (((mloc&15)>=8)?1:0);
            size_t d = (((((size_t)b*2 + mb)*8 + kc)*8 + (mloc>>4))*32 + ln)*4 + v;
            g_EAfh[d] = wh; g_EAfl[d] = wl;
        }
}

// ---------------- score GEMM: direct frag LDG (R14 form) ----------------
__global__ void __launch_bounds__(256,2) k_scoreK(const float* __restrict__ Vb)
{
    int tid = threadIdx.x, lane = tid&31, w = tid>>5, wm = w>>2, wn = w&3;
    int nb0 = blockIdx.x*16, mb = blockIdx.y, b = blockIdx.z;
    float acc[4][4][4];
    #pragma unroll
    for (int i=0;i<4;i++) for (int j=0;j<4;j++) for (int v=0;v<4;v++) acc[i][j][v]=0.f;

    #pragma unroll 1
    for (int kc = 0; kc < 8; kc++){
        uint4 ah[4], al[4]; uint2 bh[4], bl[4];
        #pragma unroll
        for (int i = 0; i < 4; i++){
            int mt = wm*4 + i;
            size_t o = (((((size_t)b*2 + mb)*8 + kc)*8 + mt)*32 + lane)*4;
            ah[i] = *(const uint4*)&g_EAfh[o];
            al[i] = *(const uint4*)&g_EAfl[o];
        }
        #pragma unroll
        for (int j = 0; j < 4; j++){
            int ntg = nb0 + wn*4 + j;
            size_t o = (((size_t)kc*32 + ntg)*32 + lane)*2;
            bh[j] = *(const uint2*)&g_Vfh[o];
            bl[j] = *(const uint2*)&g_Vfl[o];
        }
        #pragma unroll
        for (int i = 0; i < 4; i++)
            #pragma unroll
            for (int j = 0; j < 4; j++){
                mma16(acc[i][j], ah[i], bh[j]);
                mma16(acc[i][j], ah[i], bl[j]);
                mma16(acc[i][j], al[i], bh[j]);
            }
    }
    int g = lane>>2, tc = lane&3;
    int m0 = mb*128, n0 = blockIdx.x*128;
    #pragma unroll
    for (int i=0;i<4;i++)
      #pragma unroll
      for (int j=0;j<4;j++)
        #pragma unroll
        for (int r2=0;r2<2;r2++){
            int row = m0 + wm*64 + i*16 + g + 8*r2;
            int col = n0 + wn*32 + j*8 + tc*2;
            if (row < T_ && col < NTF_){
                float2 o = make_float2(acc[i][j][r2*2+0] + Vb[col],
                                       acc[i][j][r2*2+1] + Vb[col+1]);
                *(float2*)&g_score[((size_t)b*T_ + row)*NTF_ + col] = o;
            }
        }
}

// ---------------- softmax over time ----------------
__global__ void k_softmax()
{
    int b = blockIdx.x, k = threadIdx.x;
    if (k >= NTF_) return;
    float* base = g_score + (size_t)b*T_*NTF_ + k;
    float m = -FLT_MAX, s = 0.f;
    for (int t = 0; t < T_; t++){
        float x = base[t*NTF_];
        if (x > m){ s = s*__expf(m - x) + 1.f; m = x; }
        else s += __expf(x - m);
    }
    float inv = 1.f / s;
    for (int t = 0; t < T_; t++){
        float x = base[t*NTF_];
        base[t*NTF_] = __expf(x - m) * inv;
    }
}

// ---------------- context GEMM (full smem, single buffer) ----------------
__global__ void __launch_bounds__(256,2) k_context()
{
    __shared__ TSmem S;
    int tid = threadIdx.x, lane = tid&31, w = tid>>5, wm = w>>2, wn = w&3;
    int m0 = blockIdx.x*128, b = blockIdx.y;
    float acc[4][4][4];
    #pragma unroll
    for (int i=0;i<4;i++) for (int j=0;j<4;j++) for (int v=0;v<4;v++) acc[i][j][v]=0.f;

    int kpB = tid>>5, mB = tid&31;

    float ax0[4], ax1[4], bx0[4], bx1[4];
    {
        #pragma unroll
        for (int r = 0; r < 4; r++){
            int m = mB + 32*r;
            bool okm = (m0+m < NTF_);
            int t0 = 2*kpB, t1 = 2*kpB+1;
            ax0[r] = (okm && t0 < T_) ? g_score[((size_t)b*T_ + t0)*NTF_ + m0+m] : 0.f;
            ax1[r] = (okm && t1 < T_) ? g_score[((size_t)b*T_ + t1)*NTF_ + m0+m] : 0.f;
            bx0[r] = (t0 < T_) ? g_values[((size_t)b*T_ + t0)*128 + m] : 0.f;
            bx1[r] = (t1 < T_) ? g_values[((size_t)b*T_ + t1)*128 + m] : 0.f;
        }
        #pragma unroll
        for (int r = 0; r < 4; r++){
            astoreB(S.Ah, S.Al, mB+32*r, kpB, ax0[r], ax1[r]);
            bstoreB(&S.Bh[0][0][0], &S.Bl[0][0][0], kpB, mB+32*r, bx0[r], bx1[r]);
        }
    }
    __syncthreads();

    for (int c = 0; c < 16; c++){
        if (c < 15){
            int k0 = (c+1)*16;
            #pragma unroll
            for (int r = 0; r < 4; r++){
                int m = mB + 32*r;
                bool okm = (m0+m < NTF_);
                int t0 = k0 + 2*kpB, t1 = t0 + 1;
                ax0[r] = (okm && t0 < T_) ? g_score[((size_t)b*T_ + t0)*NTF_ + m0+m] : 0.f;
                ax1[r] = (okm && t1 < T_) ? g_score[((size_t)b*T_ + t1)*NTF_ + m0+m] : 0.f;
                bx0[r] = (t0 < T_) ? g_values[((size_t)b*T_ + t0)*128 + m] : 0.f;
                bx1[r] = (t1 < T_) ? g_values[((size_t)b*T_ + t1)*128 + m] : 0.f;
            }
        }
        tcomp(S, acc, lane, wm, wn);
        __syncthreads();
        if (c < 15){
            #pragma unroll
            for (int r = 0; r < 4; r++){
                astoreB(S.Ah, S.Al, mB+32*r, kpB, ax0[r], ax1[r]);
                bstoreB(&S.Bh[0][0][0], &S.Bl[0][0][0], kpB, mB+32*r, bx0[r], bx1[r]);
            }
            __syncthreads();
        }
    }
    int g = lane>>2, tc = lane&3;
    #pragma unroll
    for (int i=0;i<4;i++)
      #pragma unroll
      for (int j=0;j<4;j++)
        #pragma unroll
        for (int r2=0;r2<2;r2++){
            int row = m0 + wm*64 + i*16 + g + 8*r2;
            int col = wn*32 + j*8 + tc*2;
            if (row < NTF_){
                float2 o = make_float2(acc[i][j][r2*2+0], acc[i][j][r2*2+1]);
                *(float2*)&g_ctx[((size_t)b*NTF_ + row)*128 + col] = o;
            }
        }
}

// ---------------- per-TF heads: one fc1w load per block, 16 batch-groups ----------------
__global__ void __launch_bounds__(256) k_heads(
    const float* __restrict__ fc1w, const float* __restrict__ fc1b,
    const float* __restrict__ fc2w, const float* __restrict__ fc2b,
    float* __restrict__ out)
{
    __shared__ float fw[128][65];
    __shared__ float cs[16][128];
    __shared__ float red[16][65];
    int tid = threadIdx.x;
    int bh = blockIdx.x, k = blockIdx.y;

    for (int i = tid; i < 8192; i += 256){
        int o = i >> 7, d = i & 127;
        fw[d][o] = fc1w[(size_t)k*8192 + i];
    }

    int o = tid & 63;
    float f1b = fc1b[k*64 + o];
    float f2w = fc2w[k*64 + o];
    float f2b = fc2b[k];

    for (int grp = 0; grp < 16; grp++){
        int b0 = bh*256 + grp*16;
        __syncthreads();
        for (int i = tid; i < 2048; i += 256){
            int bi = i >> 7, d = i & 127;
            cs[bi][d] = g_ctx[((size_t)(b0+bi)*NTF_ + k)*128 + d];
        }
        __syncthreads();

        #pragma unroll
        for (int p = 0; p < 4; p++){
            int bi = (tid >> 6) + p*4;
            float acc = 0.f;
            #pragma unroll
            for (int d4 = 0; d4 < 32; d4++){
                float4 cv = *(const float4*)&cs[bi][d4*4];
                acc += fw[d4*4+0][o]*cv.x + fw[d4*4+1][o]*cv.y
                     + fw[d4*4+2][o]*cv.z + fw[d4*4+3][o]*cv.w;
            }
            float h1 = fmaxf(acc + f1b, 0.f);
            red[bi][o] = h1 * f2w;
        }
        __syncthreads();
        if (tid < 16){
            float s = f2b;
            #pragma unroll 8
            for (int oo = 0; oo < 64; oo++) s += red[tid][oo];
            out[(size_t)(b0 + tid)*NTF_ + k] = s;
        }
    }
}

// ---------------- launch ----------------
extern "C" void kernel_launch(void* const* d_in, const int* in_sizes, int n_in,
                              void* d_out, int out_size)
{
    const float* DNA    = (const float*)d_in[0];
    const float* c0w    = (const float*)d_in[1];
    const float* c0b    = (const float*)d_in[2];
    const float* bn0g   = (const float*)d_in[3];
    const float* bn0b   = (const float*)d_in[4];
    const float* bn0m   = (const float*)d_in[5];
    const float* bn0v   = (const float*)d_in[6];
    const float* c1w    = (const float*)d_in[7];
    const float* c1b    = (const float*)d_in[8];
    const float* bn1g   = (const float*)d_in[9];
    const float* bn1b   = (const float*)d_in[10];
    const float* bn1m   = (const float*)d_in[11];
    const float* bn1v   = (const float*)d_in[12];
    const float* wih_f  = (const float*)d_in[13];
    const float* whh_f  = (const float*)d_in[14];
    const float* bih_f  = (const float*)d_in[15];
    const float* bhh_f  = (const float*)d_in[16];
    const float* wih_b  = (const float*)d_in[17];
    const float* whh_b  = (const float*)d_in[18];
    const float* bih_b  = (const float*)d_in[19];
    const float* bhh_b  = (const float*)d_in[20];
    const float* W1w    = (const float*)d_in[21];
    const float* W1b    = (const float*)d_in[22];
    const float* W2w    = (const float*)d_in[23];
    const float* W2b    = (const float*)d_in[24];
    const float* Vw     = (const float*)d_in[25];
    const float* Vb     = (const float*)d_in[26];
    const float* fc1w   = (const float*)d_in[27];
    const float* fc1b   = (const float*)d_in[28];
    const float* fc2w   = (const float*)d_in[29];
    const float* fc2b   = (const float*)d_in[30];
    float* out = (float*)d_out;

    k_prep<<<512, 256>>>(W1w, W2w, Vw, wih_f, wih_b, bih_f, bhh_f, bih_b, bhh_b, c1w);
    k_conv0<<<512, 256>>>(DNA, c0w, c0b, bn0g, bn0b, bn0m, bn0v);
    k_conv1<<<988, 256>>>(c1b, bn1g, bn1b, bn1m, bn1v);
    k_xproj<<<dim3(4, 988), 256>>>();
    k_lstm<<<128, 512>>>(whh_f, whh_b);
    k_hnquery<<<512, 128>>>(W2b);
    k_keys<<<988, 256>>>(W1b);
    k_scoreK<<<dim3(2, 2, 512), 256>>>(Vb);
    k_softmax<<<512, 256>>>();
    k_context<<<dim3(2, 512), 256>>>();
    k_heads<<<dim3(2, 200), 256>>>(fc1w, fc1b, fc2w, fc2b, out);
}

// round 17
// speedup vs baseline: 1.1918x; 1.0217x over previous
#include <cuda_runtime.h>
#include <cuda_bf16.h>
#include <math.h>
#include <float.h>

#define B_    512
#define T_    247
#define C_    64
#define NTF_  200
#define LPOOL 254
#define MROWS (B_*T_)      // 126464
#define MBLK  988          // MROWS/128

typedef unsigned long long u64;

// ---------------- scratch ----------------
__device__ float g_pooled[B_*C_*LPOOL];
__device__ float g_xproj [(size_t)MROWS*512];
__device__ float g_values[MROWS*128];
__device__ float g_hT    [2*B_*64];
__device__ float g_query [B_*128];
__device__ float g_score [MROWS*NTF_];
__device__ float g_sinv  [B_*NTF_];
__device__ float g_ctx   [B_*NTF_*128];
__device__ float g_W2T [128*128];
__device__ float g_biasIH[512];
// fragment-ordered operand arrays (hi / lo bf16x2 words)
__device__ unsigned g_xAfh[(size_t)MBLK*4*8*32*4], g_xAfl[(size_t)MBLK*4*8*32*4];
__device__ unsigned g_EAfh[(size_t)B_*2*8*8*32*4], g_EAfl[(size_t)B_*2*8*8*32*4];
__device__ unsigned g_WIHfh[4*64*32*2],  g_WIHfl[4*64*32*2];
__device__ unsigned g_W1fh [8*16*32*2],  g_W1fl [8*16*32*2];
__device__ unsigned g_Vfh  [8*32*32*2],  g_Vfl  [8*32*32*2];
__device__ unsigned g_c1fh [32*8*32*2],  g_c1fl [32*8*32*2];

__device__ __forceinline__ float sigf(float x){ return 1.f/(1.f+__expf(-x)); }

// ---- packed fp32x2 helpers (FFMA2) — lstm ----
__device__ __forceinline__ u64 ffma2(u64 a, u64 b, u64 c){
    u64 d;
    asm("fma.rn.f32x2 %0, %1, %2, %3;" : "=l"(d) : "l"(a), "l"(b), "l"(c));
    return d;
}
__device__ __forceinline__ u64 pack2(float x, float y){
    u64 d;
    asm("mov.b64 %0, {%1, %2};" : "=l"(d) : "f"(x), "f"(y));
    return d;
}
__device__ __forceinline__ float2 unpack2(u64 d){
    float2 f;
    asm("mov.b64 {%0, %1}, %2;" : "=f"(f.x), "=f"(f.y) : "l"(d));
    return f;
}

// ---- bf16 2-term split ----
__device__ __forceinline__ void split2(float x0, float x1, unsigned &wh, unsigned &wl){
    unsigned hh;
    asm("cvt.rn.bf16x2.f32 %0, %1, %2;" : "=r"(hh) : "f"(x1), "f"(x0));
    float h0 = __uint_as_float(hh << 16);
    float h1 = __uint_as_float(hh & 0xffff0000u);
    float r0 = x0 - h0, r1 = x1 - h1;
    asm("cvt.rn.bf16x2.f32 %0, %1, %2;" : "=r"(wl) : "f"(r1), "f"(r0));
    wh = hh;
}
__device__ __forceinline__ void mma16(float *d, const uint4 &a, const uint2 &b){
    asm volatile("mma.sync.aligned.m16n8k16.row.col.f32.bf16.bf16.f32 "
        "{%0,%1,%2,%3}, {%4,%5,%6,%7}, {%8,%9}, {%0,%1,%2,%3};"
        : "+f"(d[0]), "+f"(d[1]), "+f"(d[2]), "+f"(d[3])
        : "r"(a.x), "r"(a.y), "r"(a.z), "r"(a.w), "r"(b.x), "r"(b.y));
}

// ---- cp.async helpers ----
__device__ __forceinline__ void cpa16(void *smem, const void *gmem){
    unsigned s = (unsigned)__cvta_generic_to_shared(smem);
    asm volatile("cp.async.cg.shared.global [%0], [%1], 16;" :: "r"(s), "l"(gmem));
}
#define CP_COMMIT asm volatile("cp.async.commit_group;" ::: "memory")
#define CP_WAIT0  asm volatile("cp.async.wait_group 0;" ::: "memory")

// smem fragment tiles
struct TSmemA { unsigned Ah[8][32][4], Al[8][32][4]; };
struct TSmem  {
    unsigned Ah[8][32][4], Al[8][32][4];
    unsigned Bh[16][33][2], Bl[16][33][2];
};

__device__ __forceinline__ void astoreW(unsigned (&Ah)[8][32][4], unsigned (&Al)[8][32][4],
                                        int m, int kp, unsigned wh, unsigned wl){
    int mt = m>>4, t = (m&7)*4 + (kp&3);
    int v = ((kp>=4)?2:0) | (((m&15)>=8)?1:0);
    Ah[mt][t][v] = wh; Al[mt][t][v] = wl;
}
__device__ __forceinline__ void bstoreW(unsigned *Bh, unsigned *Bl,
                                        int kp, int n, unsigned wh, unsigned wl){
    int idx = (n>>3)*66 + ((n&7)*4 + (kp&3))*2 + ((kp>=4)?1:0);
    Bh[idx] = wh; Bl[idx] = wl;
}
__device__ __forceinline__ void astoreB(unsigned (&Ah)[8][32][4], unsigned (&Al)[8][32][4],
                                        int m, int kp, float x0, float x1){
    unsigned wh, wl; split2(x0, x1, wh, wl);
    astoreW(Ah, Al, m, kp, wh, wl);
}
__device__ __forceinline__ void bstoreB(unsigned *Bh, unsigned *Bl,
                                        int kp, int n, float x0, float x1){
    unsigned wh, wl; split2(x0, x1, wh, wl);
    bstoreW(Bh, Bl, kp, n, wh, wl);
}

__device__ __forceinline__ void tcomp(const TSmem &S, float (&acc)[4][4][4],
                                      int lane, int wm, int wn)
{
    uint2 bh[4], bl[4];
    #pragma unroll
    for (int j = 0; j < 4; j++){
        int nt = wn*4 + j;
        bh[j] = *(const uint2*)&S.Bh[nt][lane][0];
        bl[j] = *(const uint2*)&S.Bl[nt][lane][0];
    }
    #pragma unroll
    for (int i = 0; i < 4; i++){
        int mt = wm*4 + i;
        uint4 ah = *(const uint4*)&S.Ah[mt][lane][0];
        uint4 al = *(const uint4*)&S.Al[mt][lane][0];
        #pragma unroll
        for (int j = 0; j < 4; j++){
            mma16(acc[i][j], ah, bh[j]);
            mma16(acc[i][j], ah, bl[j]);
            mma16(acc[i][j], al, bh[j]);
        }
    }
}

// ---------------- prep ----------------
__global__ void k_prep(const float* __restrict__ W1, const float* __restrict__ W2,
                       const float* __restrict__ V,
                       const float* __restrict__ wih_f, const float* __restrict__ wih_b,
                       const float* __restrict__ bih_f, const float* __restrict__ bhh_f,
                       const float* __restrict__ bih_b, const float* __restrict__ bhh_b,
                       const float* __restrict__ c1w)
{
    int idx = blockIdx.x*blockDim.x + threadIdx.x;
    if (idx < 16384){ int n = idx/128, k = idx%128; g_W2T[k*128+n] = W2[idx]; }
    if (idx < 16384){
        int kp = idx >> 9, n = idx & 511;
        float x0 = (n<256)? wih_f[n*64 + 2*kp]   : wih_b[(n-256)*64 + 2*kp];
        float x1 = (n<256)? wih_f[n*64 + 2*kp+1] : wih_b[(n-256)*64 + 2*kp+1];
        unsigned wh, wl; split2(x0, x1, wh, wl);
        int kc = kp>>3, kpA = kp&7;
        int lane = (n&7)*4 + (kpA&3), v = (kpA>=4)?1:0;
        int d = (((kc*64 + (n>>3))*32 + lane)*2) + v;
        g_WIHfh[d] = wh; g_WIHfl[d] = wl;
    }
    if (idx < 8192){
        int kp = idx >> 7, n = idx & 127;
        unsigned wh, wl; split2(W1[n*128+2*kp], W1[n*128+2*kp+1], wh, wl);
        int kc = kp>>3, kpA = kp&7;
        int lane = (n&7)*4 + (kpA&3), v = (kpA>=4)?1:0;
        int d = (((kc*16 + (n>>3))*32 + lane)*2) + v;
        g_W1fh[d] = wh; g_W1fl[d] = wl;
    }
    if (idx < 64*NTF_){
        int kp = idx / NTF_, n = idx % NTF_;
        unsigned wh, wl; split2(V[n*128+2*kp], V[n*128+2*kp+1], wh, wl);
        int kc = kp>>3, kpA = kp&7;
        int lane = (n&7)*4 + (kpA&3), v = (kpA>=4)?1:0;
        int d = (((kc*32 + (n>>3))*32 + lane)*2) + v;
        g_Vfh[d] = wh; g_Vfl[d] = wl;
    }
    if (idx < 16384){
        int kp = idx >> 6, n = idx & 63;
        unsigned wh, wl; split2(c1w[n*512+2*kp], c1w[n*512+2*kp+1], wh, wl);
        int kc = kp>>3, kpA = kp&7;
        int lane = (n&7)*4 + (kpA&3), v = (kpA>=4)?1:0;
        int d = (((kc*8 + (n>>3))*32 + lane)*2) + v;
        g_c1fh[d] = wh; g_c1fl[d] = wl;
    }
    if (idx < 512){ g_biasIH[idx] = (idx < 256) ? (bih_f[idx] + bhh_f[idx])
                                                : (bih_b[idx-256] + bhh_b[idx-256]); }
}

// ---------------- conv0 ----------------
__global__ void __launch_bounds__(256) k_conv0(
    const float* __restrict__ x, const float* __restrict__ w, const float* __restrict__ cb,
    const float* __restrict__ g, const float* __restrict__ bb,
    const float* __restrict__ mm, const float* __restrict__ vv)
{
    __shared__ float4 xs4[1024];
    int b = blockIdx.x, tid = threadIdx.x;
    const float4* in4 = (const float4*)(x + (size_t)b*4096);
    for (int i = tid; i < 1024; i += 256) xs4[i] = in4[i];

    int c = tid & 63;
    float4 wr[8];
    #pragma unroll
    for (int kk = 0; kk < 8; kk++)
        wr[kk] = make_float4(w[c*32 + 0*8 + kk], w[c*32 + 1*8 + kk],
                             w[c*32 + 2*8 + kk], w[c*32 + 3*8 + kk]);
    float scale = g[c] * rsqrtf(vv[c] + 1e-5f);
    float shift = bb[c] - mm[c]*scale;
    float cbc   = cb[c];
    __syncthreads();

    for (int idx = tid; idx < 64*LPOOL; idx += 256){
        int q = idx >> 6;
        float best = -FLT_MAX;
        #pragma unroll
        for (int dp = 0; dp < 4; dp++){
            int p = 4*q + dp;
            float acc = cbc;
            #pragma unroll
            for (int kk = 0; kk < 8; kk++){
                float4 xv = xs4[p+kk];
                acc += wr[kk].x*xv.x + wr[kk].y*xv.y + wr[kk].z*xv.z + wr[kk].w*xv.w;
            }
            best = fmaxf(best, acc*scale + shift);
        }
        g_pooled[(b*64 + c)*LPOOL + q] = fmaxf(best, 0.f);
    }
}

// ---------------- conv1 GEMM: A smem, B direct frag LDG ----------------
__global__ void __launch_bounds__(256,2) k_conv1(
    const float* __restrict__ cb,
    const float* __restrict__ gg, const float* __restrict__ bb,
    const float* __restrict__ mm, const float* __restrict__ vv)
{
    __shared__ TSmemA S;
    int tid = threadIdx.x, lane = tid&31, w = tid>>5;
    int m0  = blockIdx.x*128;
    float acc[8][4];
    #pragma unroll
    for (int j=0;j<8;j++) for (int v=0;v<4;v++) acc[j][v]=0.f;

    int mA = tid>>3, kpA = tid&7;
    int bz[4], tl[4];
    #pragma unroll
    for (int r = 0; r < 4; r++){
        int gm = m0 + mA + 32*r;
        bz[r] = gm / T_;
        tl[r] = gm - bz[r]*T_;
    }

    float ax0[4], ax1[4];
    {
        int k = 2*kpA;
        #pragma unroll
        for (int r = 0; r < 4; r++){
            int base = (bz[r]*64 + (k>>3))*LPOOL + tl[r] + (k&7);
            ax0[r] = g_pooled[base]; ax1[r] = g_pooled[base+1];
        }
        #pragma unroll
        for (int r = 0; r < 4; r++) astoreB(S.Ah, S.Al, mA+32*r, kpA, ax0[r], ax1[r]);
    }
    __syncthreads();

    for (int c = 0; c < 32; c++){
        if (c < 31){
            int k = (c+1)*16 + 2*kpA;
            #pragma unroll
            for (int r = 0; r < 4; r++){
                int base = (bz[r]*64 + (k>>3))*LPOOL + tl[r] + (k&7);
                ax0[r] = g_pooled[base]; ax1[r] = g_pooled[base+1];
            }
        }
        {
            uint4 ah = *(const uint4*)&S.Ah[w][lane][0];
            uint4 al = *(const uint4*)&S.Al[w][lane][0];
            #pragma unroll
            for (int j = 0; j < 8; j++){
                size_t o = (((size_t)c*8 + j)*32 + lane)*2;
                uint2 bh = *(const uint2*)&g_c1fh[o];
                uint2 bl = *(const uint2*)&g_c1fl[o];
                mma16(acc[j], ah, bh);
                mma16(acc[j], ah, bl);
                mma16(acc[j], al, bh);
            }
        }
        __syncthreads();
        if (c < 31){
            #pragma unroll
            for (int r = 0; r < 4; r++) astoreB(S.Ah, S.Al, mA+32*r, kpA, ax0[r], ax1[r]);
            __syncthreads();
        }
    }
    int g = lane>>2, tc = lane&3;
    #pragma unroll
    for (int j = 0; j < 8; j++){
        #pragma unroll
        for (int r2 = 0; r2 < 2; r2++){
            int row = m0 + w*16 + g + 8*r2;
            int col = j*8 + tc*2;
            float s0 = gg[col]   * rsqrtf(vv[col]   + 1e-5f);
            float s1 = gg[col+1] * rsqrtf(vv[col+1] + 1e-5f);
            float v0 = fmaxf(acc[j][r2*2+0]*s0 + bb[col]   + (cb[col]  -mm[col])  *s0, 0.f);
            float v1 = fmaxf(acc[j][r2*2+1]*s1 + bb[col+1] + (cb[col+1]-mm[col+1])*s1, 0.f);
            unsigned wh, wl; split2(v0, v1, wh, wl);
            int kp = col >> 1, kc = kp>>3, kpA2 = kp&7;
            int mblk = row>>7, mloc = row&127;
            int ln = (mloc&7)*4 + (kpA2&3);
            int v = ((kpA2>=4)?2:0) | (((mloc&15)>=8)?1:0);
            size_t d = ((((size_t)mblk*4 + kc)*8 + (mloc>>4))*32 + ln)*4 + v;
            g_xAfh[d] = wh; g_xAfl[d] = wl;
        }
    }
}

// ---------------- xproj GEMM: cp.async double-buffered frag pipeline ----------------
__global__ void __launch_bounds__(256,2) k_xproj()
{
    __shared__ unsigned sAh[2][1024], sAl[2][1024], sBh[2][1024], sBl[2][1024];
    int tid = threadIdx.x, lane = tid&31, w = tid>>5, wm = w>>2, wn = w&3;
    int nb0 = blockIdx.x*16, mblk = blockIdx.y;
    float acc[4][4][4];
    #pragma unroll
    for (int i=0;i<4;i++) for (int j=0;j<4;j++) for (int v=0;v<4;v++) acc[i][j][v]=0.f;

    {
        size_t aoff = ((size_t)mblk*4 + 0)*1024;
        size_t boff = ((size_t)0*64 + nb0)*64;
        cpa16(&sAh[0][tid*4], &g_xAfh[aoff + tid*4]);
        cpa16(&sAl[0][tid*4], &g_xAfl[aoff + tid*4]);
        cpa16(&sBh[0][tid*4], &g_WIHfh[boff + tid*4]);
        cpa16(&sBl[0][tid*4], &g_WIHfl[boff + tid*4]);
        CP_COMMIT;
    }
    #pragma unroll 1
    for (int kc = 0; kc < 4; kc++){
        CP_WAIT0;
        __syncthreads();
        if (kc < 3){
            int nb = (kc+1)&1;
            size_t aoff = ((size_t)mblk*4 + kc+1)*1024;
            size_t boff = ((size_t)(kc+1)*64 + nb0)*64;
            cpa16(&sAh[nb][tid*4], &g_xAfh[aoff + tid*4]);
            cpa16(&sAl[nb][tid*4], &g_xAfl[aoff + tid*4]);
            cpa16(&sBh[nb][tid*4], &g_WIHfh[boff + tid*4]);
            cpa16(&sBl[nb][tid*4], &g_WIHfl[boff + tid*4]);
            CP_COMMIT;
        }
        int buf = kc&1;
        uint2 bh[4], bl[4];
        #pragma unroll
        for (int j = 0; j < 4; j++){
            int nt = wn*4 + j;
            bh[j] = *(const uint2*)&sBh[buf][(nt*32+lane)*2];
            bl[j] = *(const uint2*)&sBl[buf][(nt*32+lane)*2];
        }
        #pragma unroll
        for (int i = 0; i < 4; i++){
            int mt = wm*4 + i;
            uint4 ah = *(const uint4*)&sAh[buf][(mt*32+lane)*4];
            uint4 al = *(const uint4*)&sAl[buf][(mt*32+lane)*4];
            #pragma unroll
            for (int j = 0; j < 4; j++){
                mma16(acc[i][j], ah, bh[j]);
                mma16(acc[i][j], ah, bl[j]);
                mma16(acc[i][j], al, bh[j]);
            }
        }
        __syncthreads();
    }
    int g = lane>>2, tc = lane&3;
    int m0 = mblk*128, n0 = blockIdx.x*128;
    #pragma unroll
    for (int i=0;i<4;i++)
      #pragma unroll
      for (int j=0;j<4;j++)
        #pragma unroll
        for (int r2=0;r2<2;r2++){
            int row = m0 + wm*64 + i*16 + g + 8*r2;
            int col = n0 + wn*32 + j*8 + tc*2;
            float2 o = make_float2(acc[i][j][r2*2+0] + g_biasIH[col],
                                   acc[i][j][r2*2+1] + g_biasIH[col+1]);
            *(float2*)&g_xproj[(size_t)row*512 + col] = o;
        }
}

// ---------------- LSTM recurrence ----------------
__global__ void __launch_bounds__(512) k_lstm(const float* __restrict__ whh_f,
                                              const float* __restrict__ whh_b)
{
    __shared__ float hs[2][64][4];
    __shared__ float g_sm[2][4][256];
    int b0  = blockIdx.x * 4;
    int t512 = threadIdx.x;
    int dir = t512 >> 8;
    int tid = t512 & 255;
    const float* whh = dir ? whh_b : whh_f;

    float4 w4[16];
    #pragma unroll
    for (int j4 = 0; j4 < 16; j4++) w4[j4] = *(const float4*)&whh[tid*64 + j4*4];

    hs[dir][tid>>2][tid&3] = 0.f;
    float c = 0.f, hlast = 0.f;

    int tt0 = dir ? 246 : 0;
    float xv[4];
    #pragma unroll
    for (int bi = 0; bi < 4; bi++)
        xv[bi] = g_xproj[((size_t)(b0+bi)*T_ + tt0)*512 + dir*256 + tid];
    __syncthreads();

    for (int s = 0; s < T_; s++){
        u64 acc0 = pack2(xv[0], xv[1]);
        u64 acc1 = pack2(xv[2], xv[3]);

        float xn[4];
        if (s < T_-1){
            int tt2 = dir ? (245 - s) : (s + 1);
            #pragma unroll
            for (int bi = 0; bi < 4; bi++)
                xn[bi] = g_xproj[((size_t)(b0+bi)*T_ + tt2)*512 + dir*256 + tid];
        }

        #pragma unroll
        for (int j4 = 0; j4 < 16; j4++){
            float4 w = w4[j4];
            const ulonglong2* hq = (const ulonglong2*)&hs[dir][j4*4][0];
            ulonglong2 h0 = hq[0];
            ulonglong2 h1 = hq[1];
            ulonglong2 h2 = hq[2];
            ulonglong2 h3 = hq[3];
            u64 wx = pack2(w.x, w.x);
            u64 wy = pack2(w.y, w.y);
            u64 wz = pack2(w.z, w.z);
            u64 ww = pack2(w.w, w.w);
            acc0 = ffma2(wx, h0.x, acc0); acc1 = ffma2(wx, h0.y, acc1);
            acc0 = ffma2(wy, h1.x, acc0); acc1 = ffma2(wy, h1.y, acc1);
            acc0 = ffma2(wz, h2.x, acc0); acc1 = ffma2(wz, h2.y, acc1);
            acc0 = ffma2(ww, h3.x, acc0); acc1 = ffma2(ww, h3.y, acc1);
        }
        float2 f0 = unpack2(acc0), f1 = unpack2(acc1);
        g_sm[dir][0][tid] = f0.x; g_sm[dir][1][tid] = f0.y;
        g_sm[dir][2][tid] = f1.x; g_sm[dir][3][tid] = f1.y;
        __syncthreads();

        int tv = dir ? (246 - s) : s;
        {
            int bi = tid >> 6, j = tid & 63;
            float gi = sigf(g_sm[dir][bi][j]);
            float gf = sigf(g_sm[dir][bi][64+j]);
            float gc = tanhf(g_sm[dir][bi][128+j]);
            float go = sigf(g_sm[dir][bi][192+j]);
            c = gf*c + gi*gc;
            float h = go * tanhf(c);
            hlast = h;
            hs[dir][j][bi] = h;
            g_values[((size_t)(b0+bi)*T_ + tv)*128 + dir*64 + j] = h;
        }
        __syncthreads();
        #pragma unroll
        for (int bi = 0; bi < 4; bi++) xv[bi] = xn[bi];
    }
    {
        int bi = tid >> 6, j = tid & 63;
        g_hT[dir*B_*64 + (b0+bi)*64 + j] = hlast;
    }
}

// ---------------- h_n build + query ----------------
__global__ void k_hnquery(const float* __restrict__ W2b)
{
    __shared__ float hn[128];
    int b = blockIdx.x, j = threadIdx.x;
    int half = j >> 6, jj = j & 63;
    float v;
    if (b < 256) v = g_hT[(2*b + half)*64 + jj];
    else         v = g_hT[B_*64 + (2*(b-256) + half)*64 + jj];
    hn[j] = v;
    __syncthreads();
    float acc = W2b[j];
    #pragma unroll 4
    for (int k = 0; k < 128; k++) acc += hn[k] * g_W2T[k*128 + j];
    g_query[b*128 + j] = acc;
}

// ---------------- keys GEMM + tanh: A smem, B direct ----------------
__global__ void __launch_bounds__(256,2) k_keys(const float* __restrict__ W1b)
{
    __shared__ TSmemA S;
    int tid = threadIdx.x, lane = tid&31, w = tid>>5, wm = w>>2, wn = w&3;
    int m0 = blockIdx.x*128;
    float acc[4][4][4];
    #pragma unroll
    for (int i=0;i<4;i++) for (int j=0;j<4;j++) for (int v=0;v<4;v++) acc[i][j][v]=0.f;

    int mA = tid>>3, kpA = tid&7;

    float2 ra[4];
    {
        #pragma unroll
        for (int r = 0; r < 4; r++)
            ra[r] = *(const float2*)&g_values[(size_t)(m0+mA+32*r)*128 + 2*kpA];
        #pragma unroll
        for (int r = 0; r < 4; r++) astoreB(S.Ah, S.Al, mA+32*r, kpA, ra[r].x, ra[r].y);
    }
    __syncthreads();

    for (int c = 0; c < 8; c++){
        if (c < 7){
            int k0 = (c+1)*16;
            #pragma unroll
            for (int r = 0; r < 4; r++)
                ra[r] = *(const float2*)&g_values[(size_t)(m0+mA+32*r)*128 + k0 + 2*kpA];
        }
        {
            uint2 bh[4], bl[4];
            #pragma unroll
            for (int j = 0; j < 4; j++){
                int nt = wn*4 + j;
                size_t o = (((size_t)c*16 + nt)*32 + lane)*2;
                bh[j] = *(const uint2*)&g_W1fh[o];
                bl[j] = *(const uint2*)&g_W1fl[o];
            }
            #pragma unroll
            for (int i = 0; i < 4; i++){
                int mt = wm*4 + i;
                uint4 ah = *(const uint4*)&S.Ah[mt][lane][0];
                uint4 al = *(const uint4*)&S.Al[mt][lane][0];
                #pragma unroll
                for (int j = 0; j < 4; j++){
                    mma16(acc[i][j], ah, bh[j]);
                    mma16(acc[i][j], ah, bl[j]);
                    mma16(acc[i][j], al, bh[j]);
                }
            }
        }
        __syncthreads();
        if (c < 7){
            #pragma unroll
            for (int r = 0; r < 4; r++) astoreB(S.Ah, S.Al, mA+32*r, kpA, ra[r].x, ra[r].y);
            __syncthreads();
        }
    }
    int g = lane>>2, tc = lane&3;
    #pragma unroll
    for (int i=0;i<4;i++)
      #pragma unroll
      for (int j=0;j<4;j++)
        #pragma unroll
        for (int r2=0;r2<2;r2++){
            int row = m0 + wm*64 + i*16 + g + 8*r2;
            int b = row / T_;
            int t = row - b*T_;
            int col = wn*32 + j*8 + tc*2;
            float e0 = tanhf(acc[i][j][r2*2+0] + W1b[col]   + g_query[b*128 + col]);
            float e1 = tanhf(acc[i][j][r2*2+1] + W1b[col+1] + g_query[b*128 + col+1]);
            unsigned wh, wl; split2(e0, e1, wh, wl);
            int kp = col >> 1, kc = kp>>3, kpA2 = kp&7;
            int mb = t>>7, mloc = t&127;
            int ln = (mloc&7)*4 + (kpA2&3);
            int v = ((kpA2>=4)?2:0) | (((mloc&15)>=8)?1:0);
            size_t d = (((((size_t)b*2 + mb)*8 + kc)*8 + (mloc>>4))*32 + ln)*4 + v;
            g_EAfh[d] = wh; g_EAfl[d] = wl;
        }
}

// ---------------- score GEMM: direct frag LDG, epilogue writes exp(score) ----------------
__global__ void __launch_bounds__(256,2) k_scoreK(const float* __restrict__ Vb)
{
    int tid = threadIdx.x, lane = tid&31, w = tid>>5, wm = w>>2, wn = w&3;
    int nb0 = blockIdx.x*16, mb = blockIdx.y, b = blockIdx.z;
    float acc[4][4][4];
    #pragma unroll
    for (int i=0;i<4;i++) for (int j=0;j<4;j++) for (int v=0;v<4;v++) acc[i][j][v]=0.f;

    #pragma unroll 1
    for (int kc = 0; kc < 8; kc++){
        uint4 ah[4], al[4]; uint2 bh[4], bl[4];
        #pragma unroll
        for (int i = 0; i < 4; i++){
            int mt = wm*4 + i;
            size_t o = (((((size_t)b*2 + mb)*8 + kc)*8 + mt)*32 + lane)*4;
            ah[i] = *(const uint4*)&g_EAfh[o];
            al[i] = *(const uint4*)&g_EAfl[o];
        }
        #pragma unroll
        for (int j = 0; j < 4; j++){
            int ntg = nb0 + wn*4 + j;
            size_t o = (((size_t)kc*32 + ntg)*32 + lane)*2;
            bh[j] = *(const uint2*)&g_Vfh[o];
            bl[j] = *(const uint2*)&g_Vfl[o];
        }
        #pragma unroll
        for (int i = 0; i < 4; i++)
            #pragma unroll
            for (int j = 0; j < 4; j++){
                mma16(acc[i][j], ah[i], bh[j]);
                mma16(acc[i][j], ah[i], bl[j]);
                mma16(acc[i][j], al[i], bh[j]);
            }
    }
    int g = lane>>2, tc = lane&3;
    int m0 = mb*128, n0 = blockIdx.x*128;
    #pragma unroll
    for (int i=0;i<4;i++)
      #pragma unroll
      for (int j=0;j<4;j++)
        #pragma unroll
        for (int r2=0;r2<2;r2++){
            int row = m0 + wm*64 + i*16 + g + 8*r2;
            int col = n0 + wn*32 + j*8 + tc*2;
            if (row < T_ && col < NTF_){
                float2 o = make_float2(__expf(acc[i][j][r2*2+0] + Vb[col]),
                                       __expf(acc[i][j][r2*2+1] + Vb[col+1]));
                *(float2*)&g_score[((size_t)b*T_ + row)*NTF_ + col] = o;
            }
        }
}

// ---------------- softmax sum: single read pass, store 1/sum ----------------
__global__ void k_softsum()
{
    int b = blockIdx.x, k = threadIdx.x;
    if (k >= NTF_) return;
    const float* base = g_score + (size_t)b*T_*NTF_ + k;
    float s = 0.f;
    for (int t = 0; t < T_; t++) s += base[t*NTF_];
    g_sinv[b*NTF_ + k] = 1.f / s;
}

// ---------------- context GEMM (full smem; A scaled by sinv) ----------------
__global__ void __launch_bounds__(256,2) k_context()
{
    __shared__ TSmem S;
    int tid = threadIdx.x, lane = tid&31, w = tid>>5, wm = w>>2, wn = w&3;
    int m0 = blockIdx.x*128, b = blockIdx.y;
    float acc[4][4][4];
    #pragma unroll
    for (int i=0;i<4;i++) for (int j=0;j<4;j++) for (int v=0;v<4;v++) acc[i][j][v]=0.f;

    int kpB = tid>>5, mB = tid&31;

    float sv[4];
    #pragma unroll
    for (int r = 0; r < 4; r++){
        int m = mB + 32*r;
        sv[r] = (m0+m < NTF_) ? g_sinv[b*NTF_ + m0+m] : 0.f;
    }

    float ax0[4], ax1[4], bx0[4], bx1[4];
    {
        #pragma unroll
        for (int r = 0; r < 4; r++){
            int m = mB + 32*r;
            bool okm = (m0+m < NTF_);
            int t0 = 2*kpB, t1 = 2*kpB+1;
            ax0[r] = (okm && t0 < T_) ? g_score[((size_t)b*T_ + t0)*NTF_ + m0+m]*sv[r] : 0.f;
            ax1[r] = (okm && t1 < T_) ? g_score[((size_t)b*T_ + t1)*NTF_ + m0+m]*sv[r] : 0.f;
            bx0[r] = (t0 < T_) ? g_values[((size_t)b*T_ + t0)*128 + m] : 0.f;
            bx1[r] = (t1 < T_) ? g_values[((size_t)b*T_ + t1)*128 + m] : 0.f;
        }
        #pragma unroll
        for (int r = 0; r < 4; r++){
            astoreB(S.Ah, S.Al, mB+32*r, kpB, ax0[r], ax1[r]);
            bstoreB(&S.Bh[0][0][0], &S.Bl[0][0][0], kpB, mB+32*r, bx0[r], bx1[r]);
        }
    }
    __syncthreads();

    for (int c = 0; c < 16; c++){
        if (c < 15){
            int k0 = (c+1)*16;
            #pragma unroll
            for (int r = 0; r < 4; r++){
                int m = mB + 32*r;
                bool okm = (m0+m < NTF_);
                int t0 = k0 + 2*kpB, t1 = t0 + 1;
                ax0[r] = (okm && t0 < T_) ? g_score[((size_t)b*T_ + t0)*NTF_ + m0+m]*sv[r] : 0.f;
                ax1[r] = (okm && t1 < T_) ? g_score[((size_t)b*T_ + t1)*NTF_ + m0+m]*sv[r] : 0.f;
                bx0[r] = (t0 < T_) ? g_values[((size_t)b*T_ + t0)*128 + m] : 0.f;
                bx1[r] = (t1 < T_) ? g_values[((size_t)b*T_ + t1)*128 + m] : 0.f;
            }
        }
        tcomp(S, acc, lane, wm, wn);
        __syncthreads();
        if (c < 15){
            #pragma unroll
            for (int r = 0; r < 4; r++){
                astoreB(S.Ah, S.Al, mB+32*r, kpB, ax0[r], ax1[r]);
                bstoreB(&S.Bh[0][0][0], &S.Bl[0][0][0], kpB, mB+32*r, bx0[r], bx1[r]);
            }
            __syncthreads();
        }
    }
    int g = lane>>2, tc = lane&3;
    #pragma unroll
    for (int i=0;i<4;i++)
      #pragma unroll
      for (int j=0;j<4;j++)
        #pragma unroll
        for (int r2=0;r2<2;r2++){
            int row = m0 + wm*64 + i*16 + g + 8*r2;
            int col = wn*32 + j*8 + tc*2;
            if (row < NTF_){
                float2 o = make_float2(acc[i][j][r2*2+0], acc[i][j][r2*2+1]);
                *(float2*)&g_ctx[((size_t)b*NTF_ + row)*128 + col] = o;
            }
        }
}

// ---------------- per-TF heads: one fc1w load per block, 16 batch-groups ----------------
__global__ void __launch_bounds__(256) k_heads(
    const float* __restrict__ fc1w, const float* __restrict__ fc1b,
    const float* __restrict__ fc2w, const float* __restrict__ fc2b,
    float* __restrict__ out)
{
    __shared__ float fw[128][65];
    __shared__ float cs[16][128];
    __shared__ float red[16][65];
    int tid = threadIdx.x;
    int bh = blockIdx.x, k = blockIdx.y;

    for (int i = tid; i < 8192; i += 256){
        int o = i >> 7, d = i & 127;
        fw[d][o] = fc1w[(size_t)k*8192 + i];
    }

    int o = tid & 63;
    float f1b = fc1b[k*64 + o];
    float f2w = fc2w[k*64 + o];
    float f2b = fc2b[k];

    for (int grp = 0; grp < 16; grp++){
        int b0 = bh*256 + grp*16;
        __syncthreads();
        for (int i = tid; i < 2048; i += 256){
            int bi = i >> 7, d = i & 127;
            cs[bi][d] = g_ctx[((size_t)(b0+bi)*NTF_ + k)*128 + d];
        }
        __syncthreads();

        #pragma unroll
        for (int p = 0; p < 4; p++){
            int bi = (tid >> 6) + p*4;
            float acc = 0.f;
            #pragma unroll
            for (int d4 = 0; d4 < 32; d4++){
                float4 cv = *(const float4*)&cs[bi][d4*4];
                acc += fw[d4*4+0][o]*cv.x + fw[d4*4+1][o]*cv.y
                     + fw[d4*4+2][o]*cv.z + fw[d4*4+3][o]*cv.w;
            }
            float h1 = fmaxf(acc + f1b, 0.f);
            red[bi][o] = h1 * f2w;
        }
        __syncthreads();
        if (tid < 16){
            float s = f2b;
            #pragma unroll 8
            for (int oo = 0; oo < 64; oo++) s += red[tid][oo];
            out[(size_t)(b0 + tid)*NTF_ + k] = s;
        }
    }
}

// ---------------- launch ----------------
extern "C" void kernel_launch(void* const* d_in, const int* in_sizes, int n_in,
                              void* d_out, int out_size)
{
    const float* DNA    = (const float*)d_in[0];
    const float* c0w    = (const float*)d_in[1];
    const float* c0b    = (const float*)d_in[2];
    const float* bn0g   = (const float*)d_in[3];
    const float* bn0b   = (const float*)d_in[4];
    const float* bn0m   = (const float*)d_in[5];
    const float* bn0v   = (const float*)d_in[6];
    const float* c1w    = (const float*)d_in[7];
    const float* c1b    = (const float*)d_in[8];
    const float* bn1g   = (const float*)d_in[9];
    const float* bn1b   = (const float*)d_in[10];
    const float* bn1m   = (const float*)d_in[11];
    const float* bn1v   = (const float*)d_in[12];
    const float* wih_f  = (const float*)d_in[13];
    const float* whh_f  = (const float*)d_in[14];
    const float* bih_f  = (const float*)d_in[15];
    const float* bhh_f  = (const float*)d_in[16];
    const float* wih_b  = (const float*)d_in[17];
    const float* whh_b  = (const float*)d_in[18];
    const float* bih_b  = (const float*)d_in[19];
    const float* bhh_b  = (const float*)d_in[20];
    const float* W1w    = (const float*)d_in[21];
    const float* W1b    = (const float*)d_in[22];
    const float* W2w    = (const float*)d_in[23];
    const float* W2b    = (const float*)d_in[24];
    const float* Vw     = (const float*)d_in[25];
    const float* Vb     = (const float*)d_in[26];
    const float* fc1w   = (const float*)d_in[27];
    const float* fc1b   = (const float*)d_in[28];
    const float* fc2w   = (const float*)d_in[29];
    const float* fc2b   = (const float*)d_in[30];
    float* out = (float*)d_out;

    k_prep<<<512, 256>>>(W1w, W2w, Vw, wih_f, wih_b, bih_f, bhh_f, bih_b, bhh_b, c1w);
    k_conv0<<<512, 256>>>(DNA, c0w, c0b, bn0g, bn0b, bn0m, bn0v);
    k_conv1<<<988, 256>>>(c1b, bn1g, bn1b, bn1m, bn1v);
    k_xproj<<<dim3(4, 988), 256>>>();
    k_lstm<<<128, 512>>>(whh_f, whh_b);
    k_hnquery<<<512, 128>>>(W2b);
    k_keys<<<988, 256>>>(W1b);
    k_scoreK<<<dim3(2, 2, 512), 256>>>(Vb);
    k_softsum<<<512, 256>>>();
    k_context<<<dim3(2, 512), 256>>>();
    k_heads<<<dim3(2, 200), 256>>>(fc1w, fc1b, fc2w, fc2b, out);
}